// round 13
// baseline (speedup 1.0000x reference)
#include <cuda_runtime.h>
#include <cuda_bf16.h>
#include <cstdint>

#define DM 1024
#define SQ 1025
#define BB 4
#define HH 16
#define DH 64
#define MQ (BB * SQ)      // 4100
#define MV (BB * 1024)    // 4096

typedef __nv_bfloat16 bf16;

// ---------------- scratch (device globals) ----------------------------------
__device__ __align__(256) bf16 g_Wh[8][DM * DM];
__device__ __align__(256) bf16 g_Wl[8][DM * DM];
__device__ __align__(256) bf16 g_qh[MQ * DM], g_ql[MQ * DM];
__device__ __align__(256) bf16 g_kh[MQ * DM], g_kl[MQ * DM];
__device__ __align__(256) bf16 g_eh[MQ * DM], g_el[MQ * DM];
__device__ __align__(256) bf16 g_vh[MV * DM], g_vl[MV * DM];
__device__ __align__(256) bf16 g_tqh[MQ * DM], g_tql[MQ * DM];
__device__ __align__(256) bf16 g_tkh[MQ * DM], g_tkl[MQ * DM];
__device__ __align__(256) bf16 g_qph[MQ * DM], g_qpl[MQ * DM];
__device__ __align__(256) bf16 g_kph[MQ * DM], g_kpl[MQ * DM];
__device__ __align__(256) bf16 g_vth[MV * DM], g_vtl[MV * DM];   // [bh][d][s]
__device__ __align__(256) bf16 g_ohh[MV * DM], g_ohl[MV * DM];

// ---------------- PTX helpers (generic / compute_103-legal) ------------------
__device__ __forceinline__ uint32_t smem_u32(const void* p) {
    uint32_t a;
    asm("{ .reg .u64 t; cvta.to.shared.u64 t, %1; cvt.u32.u64 %0, t; }"
        : "=r"(a) : "l"(p));
    return a;
}
__device__ __forceinline__ void ldsm4(uint32_t& r0, uint32_t& r1,
                                      uint32_t& r2, uint32_t& r3, uint32_t addr) {
    asm volatile("ldmatrix.sync.aligned.m8n8.x4.shared.b16 {%0,%1,%2,%3}, [%4];"
                 : "=r"(r0), "=r"(r1), "=r"(r2), "=r"(r3) : "r"(addr));
}
__device__ __forceinline__ void ldsm2(uint32_t& r0, uint32_t& r1, uint32_t addr) {
    asm volatile("ldmatrix.sync.aligned.m8n8.x2.shared.b16 {%0,%1}, [%2];"
                 : "=r"(r0), "=r"(r1) : "r"(addr));
}
__device__ __forceinline__ void mma_bf16(float* c, const uint32_t* a,
                                         uint32_t b0, uint32_t b1) {
    asm volatile("mma.sync.aligned.m16n8k16.row.col.f32.bf16.bf16.f32 "
                 "{%0,%1,%2,%3}, {%4,%5,%6,%7}, {%8,%9}, {%0,%1,%2,%3};"
                 : "+f"(c[0]), "+f"(c[1]), "+f"(c[2]), "+f"(c[3])
                 : "r"(a[0]), "r"(a[1]), "r"(a[2]), "r"(a[3]), "r"(b0), "r"(b1));
}
__device__ __forceinline__ void cp16(uint32_t dst, const void* src, bool pred) {
    asm volatile("cp.async.cg.shared.global [%0], [%1], 16, %2;"
                 :: "r"(dst), "l"(src), "r"(pred ? 16u : 0u) : "memory");
}
__device__ __forceinline__ void cp_commit() {
    asm volatile("cp.async.commit_group;" ::: "memory");
}
template <int N>
__device__ __forceinline__ void cp_wait() {
    asm volatile("cp.async.wait_group %0;" :: "n"(N) : "memory");
}

// ---------------- merged conversion kernels -----------------------------------
struct CJob  { const float* X; bf16* Xh; bf16* Xl; int n4; };
struct CJobs { CJob j[4]; };

__global__ void conv_split_all(CJobs jobs) {
    const CJob jb = jobs.j[blockIdx.z];
    int i = blockIdx.x * blockDim.x + threadIdx.x;
    const int stride = gridDim.x * blockDim.x;
    for (; i < jb.n4; i += stride) {
        const float4 v = ((const float4*)jb.X)[i];
        bf16 h0 = __float2bfloat16(v.x), h1 = __float2bfloat16(v.y);
        bf16 h2 = __float2bfloat16(v.z), h3 = __float2bfloat16(v.w);
        bf16 l0 = __float2bfloat16(v.x - __bfloat162float(h0));
        bf16 l1 = __float2bfloat16(v.y - __bfloat162float(h1));
        bf16 l2 = __float2bfloat16(v.z - __bfloat162float(h2));
        bf16 l3 = __float2bfloat16(v.w - __bfloat162float(h3));
        ((__nv_bfloat162*)jb.Xh)[2 * i]     = __nv_bfloat162(h0, h1);
        ((__nv_bfloat162*)jb.Xh)[2 * i + 1] = __nv_bfloat162(h2, h3);
        ((__nv_bfloat162*)jb.Xl)[2 * i]     = __nv_bfloat162(l0, l1);
        ((__nv_bfloat162*)jb.Xl)[2 * i + 1] = __nv_bfloat162(l2, l3);
    }
}

struct WTJobs { const float* W[8]; bf16* Th; bf16* Tl; };

__global__ void conv_wT_all(WTJobs jobs) {
    __shared__ float tile[32][33];
    const float* __restrict__ W = jobs.W[blockIdx.z];
    bf16* Th = jobs.Th + (size_t)blockIdx.z * DM * DM;
    bf16* Tl = jobs.Tl + (size_t)blockIdx.z * DM * DM;
    const int bx = blockIdx.x * 32, by = blockIdx.y * 32;
    const int tx = threadIdx.x, ty0 = threadIdx.y;
#pragma unroll
    for (int i = 0; i < 4; i++) {
        const int ty = ty0 + i * 8;
        tile[ty][tx] = W[(size_t)(by + ty) * DM + bx + tx];
    }
    __syncthreads();
#pragma unroll
    for (int i = 0; i < 4; i++) {
        const int ty = ty0 + i * 8;
        const float v = tile[tx][ty];
        const bf16 h = __float2bfloat16(v);
        const bf16 l = __float2bfloat16(v - __bfloat162float(h));
        Th[(size_t)(bx + ty) * DM + by + tx] = h;
        Tl[(size_t)(bx + ty) * DM + by + tx] = l;
    }
}

// ---------------- batched mma.sync GEMM (R9 config, unchanged) ------------------
#define ASTG 72
#define GBUF (128 * ASTG)
#define GEMM_SMEM (4 * GBUF * 2)

struct GemmJob {
    const bf16 *A0h, *A0l, *B0h, *B0l;
    const bf16 *A1h, *A1l, *B1h, *B1l;
    const float *bias1, *bias2;
    float *Cf; bf16 *Ch, *Cl, *Tth, *Ttl;
    int M, act;
};
struct GemmJobs3 { GemmJob j[3]; };

__global__ void __launch_bounds__(512, 2) gemm_mma(GemmJobs3 jobs)
{
    extern __shared__ __align__(16) bf16 dsm[];
    bf16* sA = dsm;
    bf16* sB = dsm + 2 * GBUF;

    const GemmJob jb = jobs.j[blockIdx.z];
    const int tid  = threadIdx.x;
    const int wid  = tid >> 5;
    const int lane = tid & 31;
    const int wm   = wid & 3;
    const int wn   = wid >> 2;
    const int col0 = blockIdx.x * 128;
    const int row0 = blockIdx.y * 128;
    const int M    = jb.M;
    if (row0 >= M) return;

    const bf16* segA[6];
    const bf16* segB[6];
    segA[0] = jb.A0h; segB[0] = jb.B0h;
    segA[1] = jb.A0h; segB[1] = jb.B0l;
    segA[2] = jb.A0l; segB[2] = jb.B0h;
    int nseg = 3;
    if (jb.A1h) {
        segA[3] = jb.A1h; segB[3] = jb.B1h;
        segA[4] = jb.A1h; segB[4] = jb.B1l;
        segA[5] = jb.A1l; segB[5] = jb.B1h;
        nseg = 6;
    }
    const int total = nseg * 16;

    auto stage = [&](int chunk, int buf) {
        const int seg = chunk >> 4;
        const int kc  = (chunk & 15) * 64;
        const bf16* __restrict__ A = segA[seg];
        const bf16* __restrict__ B = segB[seg];
        const uint32_t dA = smem_u32(sA + buf * GBUF);
        const uint32_t dB = smem_u32(sB + buf * GBUF);
#pragma unroll
        for (int it = 0; it < 2; it++) {
            const int u = tid + it * 512;
            const int row = u >> 3, cg = (u & 7) * 8;
            cp16(dA + (row * ASTG + cg) * 2,
                 A + (size_t)(row0 + row) * DM + kc + cg, row0 + row < M);
            cp16(dB + (row * ASTG + cg) * 2,
                 B + (size_t)(col0 + row) * DM + kc + cg, true);
        }
    };

    uint32_t aoff[2], boff[2];
#pragma unroll
    for (int mi = 0; mi < 2; mi++) {
        const int row = wm * 32 + mi * 16 + (lane & 15);
        aoff[mi] = (uint32_t)(row * ASTG + ((lane >> 4) << 3)) * 2;
    }
    {
        const int g = lane >> 3, r = lane & 7;
#pragma unroll
        for (int nj = 0; nj < 2; nj++) {
            const int row = wn * 32 + nj * 16 + ((g & 1) << 3) + r;
            boff[nj] = (uint32_t)(row * ASTG + ((g >> 1) << 3)) * 2;
        }
    }
    const uint32_t aBase0 = smem_u32(sA);
    const uint32_t bBase0 = smem_u32(sB);
    const uint32_t bufB = (uint32_t)GBUF * 2;

    float C[2][4][4];
#pragma unroll
    for (int mi = 0; mi < 2; mi++)
#pragma unroll
        for (int nt = 0; nt < 4; nt++)
#pragma unroll
            for (int c = 0; c < 4; c++) C[mi][nt][c] = 0.f;

    stage(0, 0);
    cp_commit();

    for (int c = 0; c < total; c++) {
        const int buf = c & 1;
        if (c + 1 < total) {
            stage(c + 1, buf ^ 1);
            cp_commit();
            cp_wait<1>();
        } else {
            cp_wait<0>();
        }
        __syncthreads();

        const uint32_t aB = aBase0 + buf * bufB;
        const uint32_t bB = bBase0 + buf * bufB;
#pragma unroll
        for (int kk = 0; kk < 4; kk++) {
            const uint32_t kb = kk * 32;
            uint32_t a[2][4];
#pragma unroll
            for (int mi = 0; mi < 2; mi++)
                ldsm4(a[mi][0], a[mi][1], a[mi][2], a[mi][3], aB + aoff[mi] + kb);
            uint32_t b[2][4];
#pragma unroll
            for (int nj = 0; nj < 2; nj++)
                ldsm4(b[nj][0], b[nj][1], b[nj][2], b[nj][3], bB + boff[nj] + kb);
#pragma unroll
            for (int mi = 0; mi < 2; mi++)
#pragma unroll
                for (int nj = 0; nj < 2; nj++) {
                    mma_bf16(C[mi][nj * 2 + 0], a[mi], b[nj][0], b[nj][2]);
                    mma_bf16(C[mi][nj * 2 + 1], a[mi], b[nj][1], b[nj][3]);
                }
        }
        __syncthreads();
    }

    const int crow = lane >> 2;
    const int ccol = (lane & 3) * 2;
#pragma unroll
    for (int mi = 0; mi < 2; mi++) {
#pragma unroll
        for (int half = 0; half < 2; half++) {
            const int r = row0 + wm * 32 + mi * 16 + crow + half * 8;
            if (r >= M) continue;
#pragma unroll
            for (int nt = 0; nt < 4; nt++) {
                const int col = col0 + wn * 32 + nt * 8 + ccol;
                float v0 = C[mi][nt][half * 2 + 0];
                float v1 = C[mi][nt][half * 2 + 1];
                v0 += jb.bias1[col];     v1 += jb.bias1[col + 1];
                if (jb.bias2) { v0 += jb.bias2[col]; v1 += jb.bias2[col + 1]; }
                if (jb.act) {
                    v0 = (v0 > 0.f) ? v0 : 0.2f * v0;
                    v1 = (v1 > 0.f) ? v1 : 0.2f * v1;
                }
                if (jb.Cf)
                    *(float2*)(jb.Cf + (size_t)r * DM + col) = make_float2(v0, v1);
                if (jb.Ch || jb.Tth) {
                    const bf16 h0 = __float2bfloat16(v0);
                    const bf16 h1 = __float2bfloat16(v1);
                    const bf16 l0 = __float2bfloat16(v0 - __bfloat162float(h0));
                    const bf16 l1 = __float2bfloat16(v1 - __bfloat162float(h1));
                    if (jb.Ch) {
                        *(__nv_bfloat162*)(jb.Ch + (size_t)r * DM + col) = __nv_bfloat162(h0, h1);
                        *(__nv_bfloat162*)(jb.Cl + (size_t)r * DM + col) = __nv_bfloat162(l0, l1);
                    }
                    if (jb.Tth) {
                        const int bb = r >> 10, s = r & 1023;
                        const int hh = col >> 6, d = col & 63;
                        const size_t base = (((size_t)(bb * HH + hh)) * 64 + d) * 1024 + s;
                        jb.Tth[base] = h0; jb.Tth[base + 1024] = h1;
                        jb.Ttl[base] = l0; jb.Ttl[base + 1024] = l1;
                    }
                }
            }
        }
    }
}

// ---------------- tensor-core attention (QR=16, 2 CTAs/SM) ----------------------
// Block (qt,h,b): 16 q rows, 512 threads.
// Score: 8 chunks of 128 k-cols, single-buffered K; 16 warps = 16 n8 groups;
//        Q fragments hoisted. V: 16 chunks of 64 s, double-buffered;
//        warps = 8 d-groups x 2 k-halves, split-k reduced in smem.
// NOTE: all smem row strides must be multiples of 8 bf16 (16B) for cp.async.
#define QR   16
#define QST  72
#define KST  72
#define VST  72                       // was 68 in R12 -> misaligned cp.async; 72 fixes it
#define ATST 72
#define SCST 1028
#define VBUF (64 * VST * 2)           // 9216 bytes per hi/lo V stage
#define O_QH   0
#define O_QL   2304
#define O_KVH  4608                   // K: 128*72*2=18432 | V: 2 bufs x 9216 = 18432
#define O_KVL  23040
#define O_ATH  41472                  // 16 x 72 x 2
#define O_ATL  43776
#define O_SC   46080                  // 16 x 1028 x 4 = 65792
#define ATT_SMEM (O_SC + QR * SCST * 4)   // 111872

__global__ void __launch_bounds__(512, 2) attn_tc(
    const bf16* __restrict__ qph, const bf16* __restrict__ qpl,
    const bf16* __restrict__ kph, const bf16* __restrict__ kpl,
    const bf16* __restrict__ vth, const bf16* __restrict__ vtl,
    const float* __restrict__ mask,
    float* __restrict__ attw, bf16* __restrict__ ohh, bf16* __restrict__ ohl)
{
    extern __shared__ __align__(16) char smem[];
    float* sc = (float*)(smem + O_SC);
    const uint32_t sb = smem_u32(smem);
    const int t = threadIdx.x, w = t >> 5, lane = t & 31;
    const int qt = blockIdx.x, h = blockIdx.y, b = blockIdx.z;
    const int bh = b * HH + h;

    // ---- load Q tile (16x64 hi+lo): 128 uint4 per h/l ----
    if (t < 256) {
        const int c = t & 127;
        const int row = c >> 3, off = (c & 7) * 8;
        const bf16* src = (t < 128 ? qph : qpl)
            + ((size_t)(b * SQ + 1 + qt * QR + row)) * DM + h * 64 + off;
        *(uint4*)(smem + (t < 128 ? O_QH : O_QL) + (row * QST + off) * 2) =
            *(const uint4*)src;
    }

    auto stage_k = [&](int c) {            // K chunk: 128 rows x 64 d, h+l
#pragma unroll
        for (int it = 0; it < 4; it++) {
            const int u2 = t + it * 512;
            const int split = u2 >> 10;
            const int u = u2 & 1023;
            const int row = u >> 3, off = (u & 7) * 8;
            const bf16* src = (split ? kpl : kph)
                + ((size_t)(b * SQ + c * 128 + row)) * DM + h * 64 + off;
            cp16(sb + (split ? O_KVL : O_KVH) + (row * KST + off) * 2, src, true);
        }
    };
    auto stage_v = [&](int c, int buf) {   // V chunk: 64 d-rows x 64 s, h+l
#pragma unroll
        for (int it = 0; it < 2; it++) {
            const int u2 = t + it * 512;
            const int split = u2 >> 9;
            const int u = u2 & 511;
            const int row = u >> 3, off = (u & 7) * 8;
            const bf16* src = (split ? vtl : vth)
                + ((size_t)(bh * 64 + row)) * 1024 + c * 64 + off;
            cp16(sb + (split ? O_KVL : O_KVH) + buf * VBUF + (row * VST + off) * 2,
                 src, true);
        }
    };

    // ---- score phase ----
    stage_k(0);
    cp_commit();
    cp_wait<0>();
    __syncthreads();    // Q + K chunk 0 visible

    // hoist Q fragments: 4 kk x (hi,lo) x 4 regs = 32 regs (rows 0-15)
    uint32_t qfh[4][4], qfl[4][4];
#pragma unroll
    for (int kk = 0; kk < 4; kk++) {
        const uint32_t qo = (uint32_t)((lane & 15) * QST
                            + kk * 16 + ((lane >> 4) << 3)) * 2;
        ldsm4(qfh[kk][0], qfh[kk][1], qfh[kk][2], qfh[kk][3], sb + O_QH + qo);
        ldsm4(qfl[kk][0], qfl[kk][1], qfl[kk][2], qfl[kk][3], sb + O_QL + qo);
    }

    // K b-frag base: warp w -> cols [w*8, w*8+8) of the 128-col chunk
    const uint32_t kobase = (uint32_t)((w * 8 + (lane & 7)) * KST
                            + (((lane >> 3) & 1) << 3)) * 2;

    for (int c = 0; c < 8; c++) {
        if (c) {    // stage chunk c (single buffer; prev mma done via sync below)
            __syncthreads();
            stage_k(c);
            cp_commit();
            cp_wait<0>();
            __syncthreads();
        }
        float C0[4] = {0.f, 0.f, 0.f, 0.f};
#pragma unroll
        for (int kk = 0; kk < 4; kk++) {
            const uint32_t kb = kk * 32;
            uint32_t bh0, bh1, bl0, bl1;
            ldsm2(bh0, bh1, sb + O_KVH + kobase + kb);
            ldsm2(bl0, bl1, sb + O_KVL + kobase + kb);
            mma_bf16(C0, qfh[kk], bh0, bh1);
            mma_bf16(C0, qfl[kk], bh0, bh1);
            mma_bf16(C0, qfh[kk], bl0, bl1);
        }
        const int colg = c * 128 + w * 8 + (lane & 3) * 2;
#pragma unroll
        for (int half = 0; half < 2; half++) {
            const int row = (lane >> 2) + half * 8;
            const float2 m = *(const float2*)(mask
                + ((size_t)b * 1024 + qt * QR + row) * 1024 + colg);
            const float v0 = fmaxf(C0[half * 2 + 0] * 0.125f, 0.f) + m.x * (-1e9f);
            const float v1 = fmaxf(C0[half * 2 + 1] * 0.125f, 0.f) + m.y * (-1e9f);
            *(float2*)&sc[row * SCST + colg] = make_float2(v0, v1);
        }
    }
    __syncthreads();

    // ---- softmax: 1 row per warp + attw write ----
    {
        const int row = w;
        float* srow = sc + row * SCST;
        float mx = -3.0e38f;
        for (int j = lane; j < 1024; j += 32) mx = fmaxf(mx, srow[j]);
#pragma unroll
        for (int o = 16; o; o >>= 1) mx = fmaxf(mx, __shfl_xor_sync(~0u, mx, o));
        float s = 0.f;
        for (int j = lane; j < 1024; j += 32) {
            const float e = __expf(srow[j] - mx);
            srow[j] = e;
            s += e;
        }
#pragma unroll
        for (int o = 16; o; o >>= 1) s += __shfl_xor_sync(~0u, s, o);
        const float inv = 1.f / s;
        float* arow = attw + (((size_t)b * HH + h) * 1024 + qt * QR + row) * 1024;
        for (int j = lane; j < 1024; j += 32) {
            const float v = srow[j] * inv;
            srow[j] = v;
            arow[j] = v;
        }
    }

    // ---- V phase: out[16,64] = att @ V; 16 chunks of 64 s ----
    float O0[4] = {0.f, 0.f, 0.f, 0.f};
    const int kko = (w >= 8) ? 2 : 0;     // k-half: kk in {kko, kko+1}
    const int n0v = (w & 7) * 8;          // d-group
    __syncthreads();                      // softmax done (sc final)
    stage_v(0, 0);
    cp_commit();
    for (int c = 0; c < 16; c++) {
        const int buf = c & 1;
        if (c) __syncthreads();           // mma(c-1) done: AT + buf free
        if (c + 1 < 16) { stage_v(c + 1, buf ^ 1); cp_commit(); }
        // convert att chunk [16 x 64] fp32 -> bf16 hi/lo (2 elems/thread)
        {
            const int idx = t * 2;
            const int row = idx >> 6, col0 = idx & 63;
            const float2 f = *(const float2*)&sc[row * SCST + c * 64 + col0];
            const bf16 h0 = __float2bfloat16(f.x);
            const bf16 h1 = __float2bfloat16(f.y);
            const bf16 l0 = __float2bfloat16(f.x - __bfloat162float(h0));
            const bf16 l1 = __float2bfloat16(f.y - __bfloat162float(h1));
            *(__nv_bfloat162*)(smem + O_ATH + (row * ATST + col0) * 2) = __nv_bfloat162(h0, h1);
            *(__nv_bfloat162*)(smem + O_ATL + (row * ATST + col0) * 2) = __nv_bfloat162(l0, l1);
        }
        if (c + 1 < 16) cp_wait<1>(); else cp_wait<0>();
        __syncthreads();
#pragma unroll
        for (int kk = 0; kk < 2; kk++) {
            const int kkk = kko + kk;
            uint32_t ah[4], al_[4];
            const uint32_t ao = (uint32_t)((lane & 15) * ATST
                                + kkk * 16 + ((lane >> 4) << 3)) * 2;
            ldsm4(ah[0], ah[1], ah[2], ah[3], sb + O_ATH + ao);
            ldsm4(al_[0], al_[1], al_[2], al_[3], sb + O_ATL + ao);
            const uint32_t vo = (uint32_t)((n0v + (lane & 7)) * VST
                                + kkk * 16 + (((lane >> 3) & 1) << 3)) * 2;
            uint32_t vh0, vh1, vl0, vl1;
            ldsm2(vh0, vh1, sb + O_KVH + buf * VBUF + vo);
            ldsm2(vl0, vl1, sb + O_KVL + buf * VBUF + vo);
            mma_bf16(O0, ah,  vh0, vh1);
            mma_bf16(O0, al_, vh0, vh1);
            mma_bf16(O0, ah,  vl0, vl1);
        }
    }
    // split-k reduction (sc area is free now)
    __syncthreads();
    float* red = sc;
    if (w >= 8) {
        float* dst = red + ((w - 8) * 32 + lane) * 4;
#pragma unroll
        for (int i = 0; i < 4; i++) dst[i] = O0[i];
    }
    __syncthreads();
    if (w < 8) {
        const float* srcp = red + (w * 32 + lane) * 4;
#pragma unroll
        for (int half = 0; half < 2; half++) {
            const int r = qt * QR + (lane >> 2) + half * 8;
            const size_t go = ((size_t)b * 1024 + r) * DM + h * 64 + n0v + (lane & 3) * 2;
            const float v0 = O0[half * 2 + 0] + srcp[half * 2 + 0];
            const float v1 = O0[half * 2 + 1] + srcp[half * 2 + 1];
            const bf16 h0 = __float2bfloat16(v0);
            const bf16 h1 = __float2bfloat16(v1);
            const bf16 l0 = __float2bfloat16(v0 - __bfloat162float(h0));
            const bf16 l1 = __float2bfloat16(v1 - __bfloat162float(h1));
            *(__nv_bfloat162*)(ohh + go) = __nv_bfloat162(h0, h1);
            *(__nv_bfloat162*)(ohl + go) = __nv_bfloat162(l0, l1);
        }
    }
}

// ---------------- launch -------------------------------------------------------
extern "C" void kernel_launch(void* const* d_in, const int* in_sizes, int n_in,
                              void* d_out, int out_size)
{
    const float* q    = (const float*)d_in[0];
    const float* k    = (const float*)d_in[1];
    const float* v    = (const float*)d_in[2];
    const float* e    = (const float*)d_in[3];
    const float* mask = (const float*)d_in[4];
    const float* W[8] = { (const float*)d_in[5],  (const float*)d_in[7],
                          (const float*)d_in[9],  (const float*)d_in[11],
                          (const float*)d_in[13], (const float*)d_in[15],
                          (const float*)d_in[17], (const float*)d_in[19] };
    const float* bq  = (const float*)d_in[6];
    const float* bq2 = (const float*)d_in[8];
    const float* bq3 = (const float*)d_in[10];
    const float* bk  = (const float*)d_in[12];
    const float* bk2 = (const float*)d_in[14];
    const float* bk3 = (const float*)d_in[16];
    const float* bv  = (const float*)d_in[18];
    const float* bo  = (const float*)d_in[20];

    float* out  = (float*)d_out;
    float* attw = out + (size_t)BB * 1024 * DM;

    bf16 *Wh, *Wl, *qh, *ql, *kh, *kl, *eh, *el, *vh, *vl;
    bf16 *tqh, *tql, *tkh, *tkl, *ohh, *ohl;
    bf16 *qph, *qpl, *kph, *kpl, *vth, *vtl;
    cudaGetSymbolAddress((void**)&Wh,  g_Wh);
    cudaGetSymbolAddress((void**)&Wl,  g_Wl);
    cudaGetSymbolAddress((void**)&qh,  g_qh);  cudaGetSymbolAddress((void**)&ql,  g_ql);
    cudaGetSymbolAddress((void**)&kh,  g_kh);  cudaGetSymbolAddress((void**)&kl,  g_kl);
    cudaGetSymbolAddress((void**)&eh,  g_eh);  cudaGetSymbolAddress((void**)&el,  g_el);
    cudaGetSymbolAddress((void**)&vh,  g_vh);  cudaGetSymbolAddress((void**)&vl,  g_vl);
    cudaGetSymbolAddress((void**)&tqh, g_tqh); cudaGetSymbolAddress((void**)&tql, g_tql);
    cudaGetSymbolAddress((void**)&tkh, g_tkh); cudaGetSymbolAddress((void**)&tkl, g_tkl);
    cudaGetSymbolAddress((void**)&qph, g_qph); cudaGetSymbolAddress((void**)&qpl, g_qpl);
    cudaGetSymbolAddress((void**)&kph, g_kph); cudaGetSymbolAddress((void**)&kpl, g_kpl);
    cudaGetSymbolAddress((void**)&vth, g_vth); cudaGetSymbolAddress((void**)&vtl, g_vtl);
    cudaGetSymbolAddress((void**)&ohh, g_ohh); cudaGetSymbolAddress((void**)&ohl, g_ohl);

    cudaFuncSetAttribute(gemm_mma, cudaFuncAttributeMaxDynamicSharedMemorySize, GEMM_SMEM);
    cudaFuncSetAttribute(attn_tc,  cudaFuncAttributeMaxDynamicSharedMemorySize, ATT_SMEM);

    {
        CJobs cj;
        cj.j[0] = { q, qh, ql, MQ * DM / 4 };
        cj.j[1] = { k, kh, kl, MQ * DM / 4 };
        cj.j[2] = { e, eh, el, MQ * DM / 4 };
        cj.j[3] = { v, vh, vl, MV * DM / 4 };
        conv_split_all<<<dim3(256, 1, 4), 256>>>(cj);
    }
    {
        WTJobs wj;
        for (int i = 0; i < 8; i++) wj.W[i] = W[i];
        wj.Th = Wh; wj.Tl = Wl;
        conv_wT_all<<<dim3(32, 32, 8), dim3(32, 8)>>>(wj);
    }

    const size_t WS = (size_t)DM * DM;
    GemmJob jz = {};

    // launch A: t_q, t_k (dual GEMMs) + vp
    {
        GemmJobs3 g = { { jz, jz, jz } };
        g.j[0] = { qh, ql, Wh + 0 * WS, Wl + 0 * WS, eh, el, Wh + 1 * WS, Wl + 1 * WS,
                   bq, bq2, nullptr, tqh, tql, nullptr, nullptr, MQ, 1 };
        g.j[1] = { kh, kl, Wh + 3 * WS, Wl + 3 * WS, eh, el, Wh + 4 * WS, Wl + 4 * WS,
                   bk, bk2, nullptr, tkh, tkl, nullptr, nullptr, MQ, 1 };
        g.j[2] = { vh, vl, Wh + 6 * WS, Wl + 6 * WS, nullptr, nullptr, nullptr, nullptr,
                   bv, nullptr, nullptr, nullptr, nullptr, vth, vtl, MV, 0 };
        gemm_mma<<<dim3(8, 33, 3), 512, GEMM_SMEM>>>(g);
    }
    // launch B: qp, kp
    {
        GemmJobs3 g = { { jz, jz, jz } };
        g.j[0] = { tqh, tql, Wh + 2 * WS, Wl + 2 * WS, nullptr, nullptr, nullptr, nullptr,
                   bq3, nullptr, nullptr, qph, qpl, nullptr, nullptr, MQ, 0 };
        g.j[1] = { tkh, tkl, Wh + 5 * WS, Wl + 5 * WS, nullptr, nullptr, nullptr, nullptr,
                   bk3, nullptr, nullptr, kph, kpl, nullptr, nullptr, MQ, 0 };
        gemm_mma<<<dim3(8, 33, 2), 512, GEMM_SMEM>>>(g);
    }

    attn_tc<<<dim3(1024 / QR, HH, BB), 512, ATT_SMEM>>>(
        qph, qpl, kph, kpl, vth, vtl, mask, attw, ohh, ohl);

    // launch C: out = oh @ Wo + bo -> fp32
    {
        GemmJobs3 g = { { jz, jz, jz } };
        g.j[0] = { ohh, ohl, Wh + 7 * WS, Wl + 7 * WS, nullptr, nullptr, nullptr, nullptr,
                   bo, nullptr, out, nullptr, nullptr, nullptr, nullptr, MV, 0 };
        gemm_mma<<<dim3(8, 32, 1), 512, GEMM_SMEM>>>(g);
    }
}

// round 14
// speedup vs baseline: 1.3883x; 1.3883x over previous
#include <cuda_runtime.h>
#include <cuda_fp16.h>
#include <cstdint>

#define DM 1024
#define SQ 1025
#define BB 4
#define HH 16
#define DH 64
#define MQ (BB * SQ)      // 4100
#define MV (BB * 1024)    // 4096
#define LOSCALE 2048.0f
#define INVLO   4.8828125e-4f   // 2^-11

typedef __half h16;

// ---------------- scratch (device globals) ----------------------------------
__device__ __align__(256) h16 g_Wh[8][DM * DM];   // weights [N,K] hi
__device__ __align__(256) h16 g_Wl[8][DM * DM];   // weights lo, pre-scaled x2048
__device__ __align__(256) h16 g_qh[MQ * DM];
__device__ __align__(256) h16 g_kh[MQ * DM];
__device__ __align__(256) h16 g_eh[MQ * DM];
__device__ __align__(256) h16 g_vh[MV * DM];
__device__ __align__(256) h16 g_tqh[MQ * DM];
__device__ __align__(256) h16 g_tkh[MQ * DM];
__device__ __align__(256) h16 g_qph[MQ * DM];
__device__ __align__(256) h16 g_kph[MQ * DM], g_kpl[MQ * DM];   // kp lo scaled
__device__ __align__(256) h16 g_vth[MV * DM], g_vtl[MV * DM];   // [bh][d][s], lo scaled
__device__ __align__(256) h16 g_ohh[MV * DM];

// ---------------- PTX helpers -------------------------------------------------
__device__ __forceinline__ uint32_t smem_u32(const void* p) {
    uint32_t a;
    asm("{ .reg .u64 t; cvta.to.shared.u64 t, %1; cvt.u32.u64 %0, t; }"
        : "=r"(a) : "l"(p));
    return a;
}
__device__ __forceinline__ void ldsm4(uint32_t& r0, uint32_t& r1,
                                      uint32_t& r2, uint32_t& r3, uint32_t addr) {
    asm volatile("ldmatrix.sync.aligned.m8n8.x4.shared.b16 {%0,%1,%2,%3}, [%4];"
                 : "=r"(r0), "=r"(r1), "=r"(r2), "=r"(r3) : "r"(addr));
}
__device__ __forceinline__ void ldsm2(uint32_t& r0, uint32_t& r1, uint32_t addr) {
    asm volatile("ldmatrix.sync.aligned.m8n8.x2.shared.b16 {%0,%1}, [%2];"
                 : "=r"(r0), "=r"(r1) : "r"(addr));
}
__device__ __forceinline__ void mma_f16(float* c, const uint32_t* a,
                                        uint32_t b0, uint32_t b1) {
    asm volatile("mma.sync.aligned.m16n8k16.row.col.f32.f16.f16.f32 "
                 "{%0,%1,%2,%3}, {%4,%5,%6,%7}, {%8,%9}, {%0,%1,%2,%3};"
                 : "+f"(c[0]), "+f"(c[1]), "+f"(c[2]), "+f"(c[3])
                 : "r"(a[0]), "r"(a[1]), "r"(a[2]), "r"(a[3]), "r"(b0), "r"(b1));
}
__device__ __forceinline__ void cp16(uint32_t dst, const void* src, bool pred) {
    asm volatile("cp.async.cg.shared.global [%0], [%1], 16, %2;"
                 :: "r"(dst), "l"(src), "r"(pred ? 16u : 0u) : "memory");
}
__device__ __forceinline__ void cp_commit() {
    asm volatile("cp.async.commit_group;" ::: "memory");
}
template <int N>
__device__ __forceinline__ void cp_wait() {
    asm volatile("cp.async.wait_group %0;" :: "n"(N) : "memory");
}

// ---------------- conversion kernels -------------------------------------------
struct CJob  { const float* X; h16* Xh; int n4; };
struct CJobs { CJob j[4]; };

__global__ void conv_h_all(CJobs jobs) {
    const CJob jb = jobs.j[blockIdx.z];
    int i = blockIdx.x * blockDim.x + threadIdx.x;
    const int stride = gridDim.x * blockDim.x;
    for (; i < jb.n4; i += stride) {
        const float4 v = ((const float4*)jb.X)[i];
        ((__half2*)jb.Xh)[2 * i]     = __floats2half2_rn(v.x, v.y);
        ((__half2*)jb.Xh)[2 * i + 1] = __floats2half2_rn(v.z, v.w);
    }
}

struct WTJobs { const float* W[8]; h16* Th; h16* Tl; };

__global__ void conv_wT_all(WTJobs jobs) {
    __shared__ float tile[32][33];
    const float* __restrict__ W = jobs.W[blockIdx.z];
    h16* Th = jobs.Th + (size_t)blockIdx.z * DM * DM;
    h16* Tl = jobs.Tl + (size_t)blockIdx.z * DM * DM;
    const int bx = blockIdx.x * 32, by = blockIdx.y * 32;
    const int tx = threadIdx.x, ty0 = threadIdx.y;
#pragma unroll
    for (int i = 0; i < 4; i++) {
        const int ty = ty0 + i * 8;
        tile[ty][tx] = W[(size_t)(by + ty) * DM + bx + tx];
    }
    __syncthreads();
#pragma unroll
    for (int i = 0; i < 4; i++) {
        const int ty = ty0 + i * 8;
        const float v = tile[tx][ty];
        const h16 h = __float2half(v);
        const h16 l = __float2half((v - __half2float(h)) * LOSCALE);
        Th[(size_t)(bx + ty) * DM + by + tx] = h;
        Tl[(size_t)(bx + ty) * DM + by + tx] = l;
    }
}

// ---------------- batched mma.sync GEMM (fp16 2-term) ---------------------------
// C = A_h @ (B_h + 2^-11 B_l')   with B_l' pre-scaled x2048.
// lo segments run first; C scaled once by 2^-11 at the segment boundary.
#define ASTG 72
#define GBUF (128 * ASTG)
#define GEMM_SMEM (4 * GBUF * 2)

struct GemmJob {
    const h16 *A0, *B0h, *B0l;
    const h16 *A1, *B1h, *B1l;
    const float *bias1, *bias2;
    float *Cf; h16 *Ch, *Cl, *Tth, *Ttl;
    int M, act;
};
struct GemmJobs3 { GemmJob j[3]; };

__global__ void __launch_bounds__(512, 2) gemm_mma(GemmJobs3 jobs)
{
    extern __shared__ __align__(16) h16 dsm[];
    h16* sA = dsm;
    h16* sB = dsm + 2 * GBUF;

    const GemmJob jb = jobs.j[blockIdx.z];
    const int tid  = threadIdx.x;
    const int wid  = tid >> 5;
    const int lane = tid & 31;
    const int wm   = wid & 3;
    const int wn   = wid >> 2;
    const int col0 = blockIdx.x * 128;
    const int row0 = blockIdx.y * 128;
    const int M    = jb.M;
    if (row0 >= M) return;

    // lo segments first, then hi segments
    const h16* segA[4];
    const h16* segB[4];
    int nseg;
    if (jb.A1) {
        segA[0] = jb.A0; segB[0] = jb.B0l;
        segA[1] = jb.A1; segB[1] = jb.B1l;
        segA[2] = jb.A0; segB[2] = jb.B0h;
        segA[3] = jb.A1; segB[3] = jb.B1h;
        nseg = 4;
    } else {
        segA[0] = jb.A0; segB[0] = jb.B0l;
        segA[1] = jb.A0; segB[1] = jb.B0h;
        nseg = 2;
    }
    const int total   = nseg * 16;
    const int scaleAt = total / 2;   // chunks of lo segments

    auto stage = [&](int chunk, int buf) {
        const int seg = chunk >> 4;
        const int kc  = (chunk & 15) * 64;
        const h16* __restrict__ A = segA[seg];
        const h16* __restrict__ B = segB[seg];
        const uint32_t dA = smem_u32(sA + buf * GBUF);
        const uint32_t dB = smem_u32(sB + buf * GBUF);
#pragma unroll
        for (int it = 0; it < 2; it++) {
            const int u = tid + it * 512;
            const int row = u >> 3, cg = (u & 7) * 8;
            cp16(dA + (row * ASTG + cg) * 2,
                 A + (size_t)(row0 + row) * DM + kc + cg, row0 + row < M);
            cp16(dB + (row * ASTG + cg) * 2,
                 B + (size_t)(col0 + row) * DM + kc + cg, true);
        }
    };

    uint32_t aoff[2], boff[2];
#pragma unroll
    for (int mi = 0; mi < 2; mi++) {
        const int row = wm * 32 + mi * 16 + (lane & 15);
        aoff[mi] = (uint32_t)(row * ASTG + ((lane >> 4) << 3)) * 2;
    }
    {
        const int g = lane >> 3, r = lane & 7;
#pragma unroll
        for (int nj = 0; nj < 2; nj++) {
            const int row = wn * 32 + nj * 16 + ((g & 1) << 3) + r;
            boff[nj] = (uint32_t)(row * ASTG + ((g >> 1) << 3)) * 2;
        }
    }
    const uint32_t aBase0 = smem_u32(sA);
    const uint32_t bBase0 = smem_u32(sB);
    const uint32_t bufB = (uint32_t)GBUF * 2;

    float C[2][4][4];
#pragma unroll
    for (int mi = 0; mi < 2; mi++)
#pragma unroll
        for (int nt = 0; nt < 4; nt++)
#pragma unroll
            for (int c = 0; c < 4; c++) C[mi][nt][c] = 0.f;

    stage(0, 0);
    cp_commit();

    for (int c = 0; c < total; c++) {
        const int buf = c & 1;
        if (c + 1 < total) {
            stage(c + 1, buf ^ 1);
            cp_commit();
            cp_wait<1>();
        } else {
            cp_wait<0>();
        }
        __syncthreads();

        const uint32_t aB = aBase0 + buf * bufB;
        const uint32_t bB = bBase0 + buf * bufB;
#pragma unroll
        for (int kk = 0; kk < 4; kk++) {
            const uint32_t kb = kk * 32;
            uint32_t a[2][4];
#pragma unroll
            for (int mi = 0; mi < 2; mi++)
                ldsm4(a[mi][0], a[mi][1], a[mi][2], a[mi][3], aB + aoff[mi] + kb);
            uint32_t b[2][4];
#pragma unroll
            for (int nj = 0; nj < 2; nj++)
                ldsm4(b[nj][0], b[nj][1], b[nj][2], b[nj][3], bB + boff[nj] + kb);
#pragma unroll
            for (int mi = 0; mi < 2; mi++)
#pragma unroll
                for (int nj = 0; nj < 2; nj++) {
                    mma_f16(C[mi][nj * 2 + 0], a[mi], b[nj][0], b[nj][2]);
                    mma_f16(C[mi][nj * 2 + 1], a[mi], b[nj][1], b[nj][3]);
                }
        }
        if (c == scaleAt - 1) {   // end of lo segments: C_lo *= 2^-11
#pragma unroll
            for (int mi = 0; mi < 2; mi++)
#pragma unroll
                for (int nt = 0; nt < 4; nt++)
#pragma unroll
                    for (int q = 0; q < 4; q++) C[mi][nt][q] *= INVLO;
        }
        __syncthreads();
    }

    // ---- epilogue ----
    const int crow = lane >> 2;
    const int ccol = (lane & 3) * 2;
#pragma unroll
    for (int mi = 0; mi < 2; mi++) {
#pragma unroll
        for (int half = 0; half < 2; half++) {
            const int r = row0 + wm * 32 + mi * 16 + crow + half * 8;
            if (r >= M) continue;
#pragma unroll
            for (int nt = 0; nt < 4; nt++) {
                const int col = col0 + wn * 32 + nt * 8 + ccol;
                float v0 = C[mi][nt][half * 2 + 0];
                float v1 = C[mi][nt][half * 2 + 1];
                v0 += jb.bias1[col];     v1 += jb.bias1[col + 1];
                if (jb.bias2) { v0 += jb.bias2[col]; v1 += jb.bias2[col + 1]; }
                if (jb.act) {
                    v0 = (v0 > 0.f) ? v0 : 0.2f * v0;
                    v1 = (v1 > 0.f) ? v1 : 0.2f * v1;
                }
                if (jb.Cf)
                    *(float2*)(jb.Cf + (size_t)r * DM + col) = make_float2(v0, v1);
                if (jb.Ch) {
                    const h16 h0 = __float2half(v0);
                    const h16 h1 = __float2half(v1);
                    *(__half2*)(jb.Ch + (size_t)r * DM + col) = __halves2half2(h0, h1);
                    if (jb.Cl) {
                        const h16 l0 = __float2half((v0 - __half2float(h0)) * LOSCALE);
                        const h16 l1 = __float2half((v1 - __half2float(h1)) * LOSCALE);
                        *(__half2*)(jb.Cl + (size_t)r * DM + col) = __halves2half2(l0, l1);
                    }
                }
                if (jb.Tth) {   // per-head transposed hi/lo: vt[bh][d][s]
                    const h16 h0 = __float2half(v0);
                    const h16 h1 = __float2half(v1);
                    const h16 l0 = __float2half((v0 - __half2float(h0)) * LOSCALE);
                    const h16 l1 = __float2half((v1 - __half2float(h1)) * LOSCALE);
                    const int bb = r >> 10, s = r & 1023;
                    const int hh = col >> 6, d = col & 63;
                    const size_t base = (((size_t)(bb * HH + hh)) * 64 + d) * 1024 + s;
                    jb.Tth[base] = h0; jb.Tth[base + 1024] = h1;
                    jb.Ttl[base] = l0; jb.Ttl[base + 1024] = l1;
                }
            }
        }
    }
}

// ---------------- tensor-core attention (QR=32, fp16 2-term) --------------------
// scores = Qh·Kh + 2^-11·(Qh·Kl'); out = ATh·Vh + 2^-11·(ATh·Vl').
#define QR   32
#define QST  72
#define KST  72
#define VST  136
#define ATST 136
#define SCST 1028
#define KVBUF 18432
#define O_QH   0
#define O_KVH  4608                   // 2 bufs x 18432
#define O_KVL  41472                  // 2 bufs x 18432
#define O_ATH  78336                  // 32 x 136 x 2 = 8704
#define O_SC   87040
#define ATT_SMEM (O_SC + QR * SCST * 4)   // 218624

__global__ void __launch_bounds__(512, 1) attn_tc(
    const h16* __restrict__ qph,
    const h16* __restrict__ kph, const h16* __restrict__ kpl,
    const h16* __restrict__ vth, const h16* __restrict__ vtl,
    const float* __restrict__ mask,
    float* __restrict__ attw, h16* __restrict__ ohh)
{
    extern __shared__ __align__(16) char smem[];
    float* sc = (float*)(smem + O_SC);
    const uint32_t sb = smem_u32(smem);
    const int t = threadIdx.x, w = t >> 5, lane = t & 31;
    const int qt = blockIdx.x, h = blockIdx.y, b = blockIdx.z;
    const int bh = b * HH + h;

    // ---- load Q tile (32x64 hi): 256 uint4 ----
    if (t < 256) {
        const int row = t >> 3, off = (t & 7) * 8;
        const h16* src = qph + ((size_t)(b * SQ + 1 + qt * QR + row)) * DM + h * 64 + off;
        *(uint4*)(smem + O_QH + (row * QST + off) * 2) = *(const uint4*)src;
    }

    auto stage_k = [&](int c, int buf) {
#pragma unroll
        for (int it = 0; it < 4; it++) {
            const int u2 = t + it * 512;
            const int split = u2 >> 10;
            const int u = u2 & 1023;
            const int row = u >> 3, off = (u & 7) * 8;
            const h16* src = (split ? kpl : kph)
                + ((size_t)(b * SQ + c * 128 + row)) * DM + h * 64 + off;
            cp16(sb + (split ? O_KVL : O_KVH) + buf * KVBUF + (row * KST + off) * 2,
                 src, true);
        }
    };
    auto stage_v = [&](int c, int buf) {
#pragma unroll
        for (int it = 0; it < 4; it++) {
            const int u2 = t + it * 512;
            const int split = u2 >> 10;
            const int u = u2 & 1023;
            const int row = u >> 4, off = (u & 15) * 8;
            const h16* src = (split ? vtl : vth)
                + ((size_t)(bh * 64 + row)) * 1024 + c * 128 + off;
            cp16(sb + (split ? O_KVL : O_KVH) + buf * KVBUF + (row * VST + off) * 2,
                 src, true);
        }
    };

    // ---- score phase: warps (2 row-halves x 8 col-groups), Q hoisted ----
    const int wrow = w >> 3;
    const int wcol = w & 7;
    const int n0s = wcol * 16;

    stage_k(0, 0);
    cp_commit();
    __syncthreads();   // Q visible

    uint32_t qfh[4][4];
#pragma unroll
    for (int kk = 0; kk < 4; kk++) {
        const uint32_t qo = (uint32_t)((wrow * 16 + (lane & 15)) * QST
                            + kk * 16 + ((lane >> 4) << 3)) * 2;
        ldsm4(qfh[kk][0], qfh[kk][1], qfh[kk][2], qfh[kk][3], sb + O_QH + qo);
    }

    const int kg = lane >> 3, kr = lane & 7;
    const uint32_t kobase = (uint32_t)((n0s + ((kg & 1) << 3) + kr) * KST
                            + ((kg >> 1) << 3)) * 2;

    for (int c = 0; c < 8; c++) {
        const int buf = c & 1;
        if (c) __syncthreads();
        if (c + 1 < 8) { stage_k(c + 1, buf ^ 1); cp_commit(); cp_wait<1>(); }
        else           { cp_wait<0>(); }
        __syncthreads();

        float Cm[2][4] = {{0.f,0.f,0.f,0.f},{0.f,0.f,0.f,0.f}};
        float Cc[2][4] = {{0.f,0.f,0.f,0.f},{0.f,0.f,0.f,0.f}};
        const uint32_t kh_base = sb + O_KVH + buf * KVBUF + kobase;
        const uint32_t kl_base = sb + O_KVL + buf * KVBUF + kobase;
#pragma unroll
        for (int kk = 0; kk < 4; kk++) {
            const uint32_t kb = kk * 32;
            uint32_t bh_[4], bl_[4];
            ldsm4(bh_[0], bh_[1], bh_[2], bh_[3], kh_base + kb);
            ldsm4(bl_[0], bl_[1], bl_[2], bl_[3], kl_base + kb);
#pragma unroll
            for (int ng = 0; ng < 2; ng++) {
                mma_f16(Cm[ng], qfh[kk], bh_[ng], bh_[ng + 2]);
                mma_f16(Cc[ng], qfh[kk], bl_[ng], bl_[ng + 2]);
            }
        }
#pragma unroll
        for (int ng = 0; ng < 2; ng++)
#pragma unroll
            for (int half = 0; half < 2; half++) {
                const int row = wrow * 16 + (lane >> 2) + half * 8;
                const int col = c * 128 + n0s + ng * 8 + (lane & 3) * 2;
                const float2 m = *(const float2*)(mask
                    + ((size_t)b * 1024 + qt * QR + row) * 1024 + col);
                const float s0 = Cm[ng][half * 2 + 0] + Cc[ng][half * 2 + 0] * INVLO;
                const float s1 = Cm[ng][half * 2 + 1] + Cc[ng][half * 2 + 1] * INVLO;
                const float v0 = fmaxf(s0 * 0.125f, 0.f) + m.x * (-1e9f);
                const float v1 = fmaxf(s1 * 0.125f, 0.f) + m.y * (-1e9f);
                *(float2*)&sc[row * SCST + col] = make_float2(v0, v1);
            }
    }
    __syncthreads();

    // ---- softmax (warp per 2 rows) + attw write ----
    {
        const size_t abase = (((size_t)b * HH + h) * 1024 + qt * QR) * 1024;
#pragma unroll
        for (int rr = 0; rr < 2; rr++) {
            const int row = w * 2 + rr;
            float* srow = sc + row * SCST;
            float mx = -3.0e38f;
            for (int j = lane; j < 1024; j += 32) mx = fmaxf(mx, srow[j]);
#pragma unroll
            for (int o = 16; o; o >>= 1) mx = fmaxf(mx, __shfl_xor_sync(~0u, mx, o));
            float s = 0.f;
            for (int j = lane; j < 1024; j += 32) {
                const float e = __expf(srow[j] - mx);
                srow[j] = e;
                s += e;
            }
#pragma unroll
            for (int o = 16; o; o >>= 1) s += __shfl_xor_sync(~0u, s, o);
            const float inv = 1.f / s;
            float* arow = attw + abase + (size_t)row * 1024;
            for (int j = lane; j < 1024; j += 32) {
                const float v = srow[j] * inv;
                srow[j] = v;
                arow[j] = v;
            }
        }
    }

    // ---- V phase: out[32,64] = att @ V; split-k across warp halves ----
    float Om[2][4] = {{0.f,0.f,0.f,0.f},{0.f,0.f,0.f,0.f}};
    float Oc[2][4] = {{0.f,0.f,0.f,0.f},{0.f,0.f,0.f,0.f}};
    const int kko = (w >= 8) ? 4 : 0;
    const int n0v = (w & 7) * 8;
    stage_v(0, 0);
    cp_commit();
    for (int c = 0; c < 8; c++) {
        const int buf = c & 1;
        __syncthreads();
        if (c + 1 < 8) { stage_v(c + 1, buf ^ 1); cp_commit(); }
        // convert att chunk [32x128] fp32 -> fp16 hi (8 elems/thread)
        {
            const int idx = t * 8;
            const int row = idx >> 7, col0 = idx & 127;
            const float* s4 = &sc[row * SCST + c * 128 + col0];
            const float4 f0 = *(const float4*)s4;
            const float4 f1 = *(const float4*)(s4 + 4);
            __half2 ph[4];
            ph[0] = __floats2half2_rn(f0.x, f0.y);
            ph[1] = __floats2half2_rn(f0.z, f0.w);
            ph[2] = __floats2half2_rn(f1.x, f1.y);
            ph[3] = __floats2half2_rn(f1.z, f1.w);
            *(uint4*)(smem + O_ATH + (row * ATST + col0) * 2) = *(uint4*)ph;
        }
        if (c + 1 < 8) cp_wait<1>(); else cp_wait<0>();
        __syncthreads();
#pragma unroll
        for (int kk = 0; kk < 4; kk++) {
            const int kkk = kko + kk;
            uint32_t ah[2][4];
#pragma unroll
            for (int mi = 0; mi < 2; mi++) {
                const uint32_t ao = (uint32_t)((mi * 16 + (lane & 15)) * ATST
                                    + kkk * 16 + ((lane >> 4) << 3)) * 2;
                ldsm4(ah[mi][0], ah[mi][1], ah[mi][2], ah[mi][3], sb + O_ATH + ao);
            }
            const uint32_t vo = (uint32_t)((n0v + (lane & 7)) * VST
                                + kkk * 16 + (((lane >> 3) & 1) << 3)) * 2;
            uint32_t vh0, vh1, vl0, vl1;
            ldsm2(vh0, vh1, sb + O_KVH + buf * KVBUF + vo);
            ldsm2(vl0, vl1, sb + O_KVL + buf * KVBUF + vo);
#pragma unroll
            for (int mi = 0; mi < 2; mi++) {
                mma_f16(Om[mi], ah[mi], vh0, vh1);
                mma_f16(Oc[mi], ah[mi], vl0, vl1);
            }
        }
    }
    // combine correction, split-k reduction
#pragma unroll
    for (int mi = 0; mi < 2; mi++)
#pragma unroll
        for (int i = 0; i < 4; i++) Om[mi][i] += Oc[mi][i] * INVLO;
    __syncthreads();
    float* red = (float*)(smem + O_ATH);
    if (w >= 8) {
        float* dst = red + ((w - 8) * 32 + lane) * 8;
#pragma unroll
        for (int mi = 0; mi < 2; mi++)
#pragma unroll
            for (int i = 0; i < 4; i++) dst[mi * 4 + i] = Om[mi][i];
    }
    __syncthreads();
    if (w < 8) {
        const float* srcp = red + (w * 32 + lane) * 8;
#pragma unroll
        for (int mi = 0; mi < 2; mi++)
#pragma unroll
            for (int half = 0; half < 2; half++) {
                const int r = qt * QR + mi * 16 + (lane >> 2) + half * 8;
                const size_t go = ((size_t)b * 1024 + r) * DM + h * 64 + n0v + (lane & 3) * 2;
                const float v0 = Om[mi][half * 2 + 0] + srcp[mi * 4 + half * 2 + 0];
                const float v1 = Om[mi][half * 2 + 1] + srcp[mi * 4 + half * 2 + 1];
                *(__half2*)(ohh + go) = __floats2half2_rn(v0, v1);
            }
    }
}

// ---------------- launch -------------------------------------------------------
extern "C" void kernel_launch(void* const* d_in, const int* in_sizes, int n_in,
                              void* d_out, int out_size)
{
    const float* q    = (const float*)d_in[0];
    const float* k    = (const float*)d_in[1];
    const float* v    = (const float*)d_in[2];
    const float* e    = (const float*)d_in[3];
    const float* mask = (const float*)d_in[4];
    const float* W[8] = { (const float*)d_in[5],  (const float*)d_in[7],
                          (const float*)d_in[9],  (const float*)d_in[11],
                          (const float*)d_in[13], (const float*)d_in[15],
                          (const float*)d_in[17], (const float*)d_in[19] };
    const float* bq  = (const float*)d_in[6];
    const float* bq2 = (const float*)d_in[8];
    const float* bq3 = (const float*)d_in[10];
    const float* bk  = (const float*)d_in[12];
    const float* bk2 = (const float*)d_in[14];
    const float* bk3 = (const float*)d_in[16];
    const float* bv  = (const float*)d_in[18];
    const float* bo  = (const float*)d_in[20];

    float* out  = (float*)d_out;
    float* attw = out + (size_t)BB * 1024 * DM;

    h16 *Wh, *Wl, *qh, *kh, *eh, *vh, *tqh, *tkh;
    h16 *qph, *kph, *kpl, *vth, *vtl, *ohh;
    cudaGetSymbolAddress((void**)&Wh,  g_Wh);
    cudaGetSymbolAddress((void**)&Wl,  g_Wl);
    cudaGetSymbolAddress((void**)&qh,  g_qh);
    cudaGetSymbolAddress((void**)&kh,  g_kh);
    cudaGetSymbolAddress((void**)&eh,  g_eh);
    cudaGetSymbolAddress((void**)&vh,  g_vh);
    cudaGetSymbolAddress((void**)&tqh, g_tqh);
    cudaGetSymbolAddress((void**)&tkh, g_tkh);
    cudaGetSymbolAddress((void**)&qph, g_qph);
    cudaGetSymbolAddress((void**)&kph, g_kph); cudaGetSymbolAddress((void**)&kpl, g_kpl);
    cudaGetSymbolAddress((void**)&vth, g_vth); cudaGetSymbolAddress((void**)&vtl, g_vtl);
    cudaGetSymbolAddress((void**)&ohh, g_ohh);

    cudaFuncSetAttribute(gemm_mma, cudaFuncAttributeMaxDynamicSharedMemorySize, GEMM_SMEM);
    cudaFuncSetAttribute(attn_tc,  cudaFuncAttributeMaxDynamicSharedMemorySize, ATT_SMEM);

    {
        CJobs cj;
        cj.j[0] = { q, qh, MQ * DM / 4 };
        cj.j[1] = { k, kh, MQ * DM / 4 };
        cj.j[2] = { e, eh, MQ * DM / 4 };
        cj.j[3] = { v, vh, MV * DM / 4 };
        conv_h_all<<<dim3(256, 1, 4), 256>>>(cj);
    }
    {
        WTJobs wj;
        for (int i = 0; i < 8; i++) wj.W[i] = W[i];
        wj.Th = Wh; wj.Tl = Wl;
        conv_wT_all<<<dim3(32, 32, 8), dim3(32, 8)>>>(wj);
    }

    const size_t WS = (size_t)DM * DM;
    GemmJob jz = {};

    // launch A: t_q, t_k (dual) + vp
    {
        GemmJobs3 g = { { jz, jz, jz } };
        g.j[0] = { qh, Wh + 0 * WS, Wl + 0 * WS, eh, Wh + 1 * WS, Wl + 1 * WS,
                   bq, bq2, nullptr, tqh, nullptr, nullptr, nullptr, MQ, 1 };
        g.j[1] = { kh, Wh + 3 * WS, Wl + 3 * WS, eh, Wh + 4 * WS, Wl + 4 * WS,
                   bk, bk2, nullptr, tkh, nullptr, nullptr, nullptr, MQ, 1 };
        g.j[2] = { vh, Wh + 6 * WS, Wl + 6 * WS, nullptr, nullptr, nullptr,
                   bv, nullptr, nullptr, nullptr, nullptr, vth, vtl, MV, 0 };
        gemm_mma<<<dim3(8, 33, 3), 512, GEMM_SMEM>>>(g);
    }
    // launch B: qp (hi), kp (hi+lo)
    {
        GemmJobs3 g = { { jz, jz, jz } };
        g.j[0] = { tqh, Wh + 2 * WS, Wl + 2 * WS, nullptr, nullptr, nullptr,
                   bq3, nullptr, nullptr, qph, nullptr, nullptr, nullptr, MQ, 0 };
        g.j[1] = { tkh, Wh + 5 * WS, Wl + 5 * WS, nullptr, nullptr, nullptr,
                   bk3, nullptr, nullptr, kph, kpl, nullptr, nullptr, MQ, 0 };
        gemm_mma<<<dim3(8, 33, 2), 512, GEMM_SMEM>>>(g);
    }

    attn_tc<<<dim3(1024 / QR, HH, BB), 512, ATT_SMEM>>>(
        qph, kph, kpl, vth, vtl, mask, attw, ohh);

    // launch C: out = oh @ Wo + bo -> fp32
    {
        GemmJobs3 g = { { jz, jz, jz } };
        g.j[0] = { ohh, Wh + 7 * WS, Wl + 7 * WS, nullptr, nullptr, nullptr,
                   bo, nullptr, out, nullptr, nullptr, nullptr, nullptr, MV, 0 };
        gemm_mma<<<dim3(8, 32, 1), 512, GEMM_SMEM>>>(g);
    }
}

// round 15
// speedup vs baseline: 1.4403x; 1.0375x over previous
#include <cuda_runtime.h>
#include <cuda_fp16.h>
#include <cstdint>

#define DM 1024
#define SQ 1025
#define BB 4
#define HH 16
#define DH 64
#define MQ (BB * SQ)      // 4100
#define MV (BB * 1024)    // 4096
#define LOSCALE 2048.0f
#define INVLO   4.8828125e-4f   // 2^-11

typedef __half h16;

// ---------------- scratch (device globals) ----------------------------------
__device__ __align__(256) h16 g_Wh[8][DM * DM];   // weights [N,K] hi
__device__ __align__(256) h16 g_Wl[8][DM * DM];   // weights lo, pre-scaled x2048
__device__ __align__(256) h16 g_qh[MQ * DM];
__device__ __align__(256) h16 g_kh[MQ * DM];
__device__ __align__(256) h16 g_eh[MQ * DM];
__device__ __align__(256) h16 g_vh[MV * DM];
__device__ __align__(256) h16 g_tqh[MQ * DM];
__device__ __align__(256) h16 g_tkh[MQ * DM];
__device__ __align__(256) h16 g_qph[MQ * DM];
__device__ __align__(256) h16 g_kph[MQ * DM], g_kpl[MQ * DM];   // kp lo scaled
__device__ __align__(256) h16 g_vth[MV * DM];                    // [bh][d][s] hi only
__device__ __align__(256) h16 g_ohh[MV * DM];

// ---------------- PTX helpers -------------------------------------------------
__device__ __forceinline__ uint32_t smem_u32(const void* p) {
    uint32_t a;
    asm("{ .reg .u64 t; cvta.to.shared.u64 t, %1; cvt.u32.u64 %0, t; }"
        : "=r"(a) : "l"(p));
    return a;
}
__device__ __forceinline__ void ldsm4(uint32_t& r0, uint32_t& r1,
                                      uint32_t& r2, uint32_t& r3, uint32_t addr) {
    asm volatile("ldmatrix.sync.aligned.m8n8.x4.shared.b16 {%0,%1,%2,%3}, [%4];"
                 : "=r"(r0), "=r"(r1), "=r"(r2), "=r"(r3) : "r"(addr));
}
__device__ __forceinline__ void ldsm2(uint32_t& r0, uint32_t& r1, uint32_t addr) {
    asm volatile("ldmatrix.sync.aligned.m8n8.x2.shared.b16 {%0,%1}, [%2];"
                 : "=r"(r0), "=r"(r1) : "r"(addr));
}
__device__ __forceinline__ void mma_f16(float* c, const uint32_t* a,
                                        uint32_t b0, uint32_t b1) {
    asm volatile("mma.sync.aligned.m16n8k16.row.col.f32.f16.f16.f32 "
                 "{%0,%1,%2,%3}, {%4,%5,%6,%7}, {%8,%9}, {%0,%1,%2,%3};"
                 : "+f"(c[0]), "+f"(c[1]), "+f"(c[2]), "+f"(c[3])
                 : "r"(a[0]), "r"(a[1]), "r"(a[2]), "r"(a[3]), "r"(b0), "r"(b1));
}
__device__ __forceinline__ void cp16(uint32_t dst, const void* src, bool pred) {
    asm volatile("cp.async.cg.shared.global [%0], [%1], 16, %2;"
                 :: "r"(dst), "l"(src), "r"(pred ? 16u : 0u) : "memory");
}
__device__ __forceinline__ void cp_commit() {
    asm volatile("cp.async.commit_group;" ::: "memory");
}
template <int N>
__device__ __forceinline__ void cp_wait() {
    asm volatile("cp.async.wait_group %0;" :: "n"(N) : "memory");
}

// ---------------- conversion kernels -------------------------------------------
struct CJob  { const float* X; h16* Xh; int n4; };
struct CJobs { CJob j[4]; };

__global__ void conv_h_all(CJobs jobs) {
    const CJob jb = jobs.j[blockIdx.z];
    int i = blockIdx.x * blockDim.x + threadIdx.x;
    const int stride = gridDim.x * blockDim.x;
    for (; i < jb.n4; i += stride) {
        const float4 v = ((const float4*)jb.X)[i];
        ((__half2*)jb.Xh)[2 * i]     = __floats2half2_rn(v.x, v.y);
        ((__half2*)jb.Xh)[2 * i + 1] = __floats2half2_rn(v.z, v.w);
    }
}

struct WTJobs { const float* W[8]; h16* Th; h16* Tl; };

__global__ void conv_wT_all(WTJobs jobs) {
    __shared__ float tile[32][33];
    const float* __restrict__ W = jobs.W[blockIdx.z];
    h16* Th = jobs.Th + (size_t)blockIdx.z * DM * DM;
    h16* Tl = jobs.Tl + (size_t)blockIdx.z * DM * DM;
    const int bx = blockIdx.x * 32, by = blockIdx.y * 32;
    const int tx = threadIdx.x, ty0 = threadIdx.y;
#pragma unroll
    for (int i = 0; i < 4; i++) {
        const int ty = ty0 + i * 8;
        tile[ty][tx] = W[(size_t)(by + ty) * DM + bx + tx];
    }
    __syncthreads();
#pragma unroll
    for (int i = 0; i < 4; i++) {
        const int ty = ty0 + i * 8;
        const float v = tile[tx][ty];
        const h16 h = __float2half(v);
        const h16 l = __float2half((v - __half2float(h)) * LOSCALE);
        Th[(size_t)(bx + ty) * DM + by + tx] = h;
        Tl[(size_t)(bx + ty) * DM + by + tx] = l;
    }
}

// ---------------- batched mma.sync GEMM (fp16 2-term) ---------------------------
#define ASTG 72
#define GBUF (128 * ASTG)
#define GEMM_SMEM (4 * GBUF * 2)

struct GemmJob {
    const h16 *A0, *B0h, *B0l;
    const h16 *A1, *B1h, *B1l;
    const float *bias1, *bias2;
    float *Cf; h16 *Ch, *Cl, *Tth, *Ttl;
    int M, act;
};
struct GemmJobs3 { GemmJob j[3]; };

__global__ void __launch_bounds__(512, 2) gemm_mma(GemmJobs3 jobs)
{
    extern __shared__ __align__(16) h16 dsm[];
    h16* sA = dsm;
    h16* sB = dsm + 2 * GBUF;

    const GemmJob jb = jobs.j[blockIdx.z];
    const int tid  = threadIdx.x;
    const int wid  = tid >> 5;
    const int lane = tid & 31;
    const int wm   = wid & 3;
    const int wn   = wid >> 2;
    const int col0 = blockIdx.x * 128;
    const int row0 = blockIdx.y * 128;
    const int M    = jb.M;
    if (row0 >= M) return;

    // lo segments first, then hi segments
    const h16* segA[4];
    const h16* segB[4];
    int nseg;
    if (jb.A1) {
        segA[0] = jb.A0; segB[0] = jb.B0l;
        segA[1] = jb.A1; segB[1] = jb.B1l;
        segA[2] = jb.A0; segB[2] = jb.B0h;
        segA[3] = jb.A1; segB[3] = jb.B1h;
        nseg = 4;
    } else {
        segA[0] = jb.A0; segB[0] = jb.B0l;
        segA[1] = jb.A0; segB[1] = jb.B0h;
        nseg = 2;
    }
    const int total   = nseg * 16;
    const int scaleAt = total / 2;

    auto stage = [&](int chunk, int buf) {
        const int seg = chunk >> 4;
        const int kc  = (chunk & 15) * 64;
        const h16* __restrict__ A = segA[seg];
        const h16* __restrict__ B = segB[seg];
        const uint32_t dA = smem_u32(sA + buf * GBUF);
        const uint32_t dB = smem_u32(sB + buf * GBUF);
#pragma unroll
        for (int it = 0; it < 2; it++) {
            const int u = tid + it * 512;
            const int row = u >> 3, cg = (u & 7) * 8;
            cp16(dA + (row * ASTG + cg) * 2,
                 A + (size_t)(row0 + row) * DM + kc + cg, row0 + row < M);
            cp16(dB + (row * ASTG + cg) * 2,
                 B + (size_t)(col0 + row) * DM + kc + cg, true);
        }
    };

    uint32_t aoff[2], boff[2];
#pragma unroll
    for (int mi = 0; mi < 2; mi++) {
        const int row = wm * 32 + mi * 16 + (lane & 15);
        aoff[mi] = (uint32_t)(row * ASTG + ((lane >> 4) << 3)) * 2;
    }
    {
        const int g = lane >> 3, r = lane & 7;
#pragma unroll
        for (int nj = 0; nj < 2; nj++) {
            const int row = wn * 32 + nj * 16 + ((g & 1) << 3) + r;
            boff[nj] = (uint32_t)(row * ASTG + ((g >> 1) << 3)) * 2;
        }
    }
    const uint32_t aBase0 = smem_u32(sA);
    const uint32_t bBase0 = smem_u32(sB);
    const uint32_t bufB = (uint32_t)GBUF * 2;

    float C[2][4][4];
#pragma unroll
    for (int mi = 0; mi < 2; mi++)
#pragma unroll
        for (int nt = 0; nt < 4; nt++)
#pragma unroll
            for (int c = 0; c < 4; c++) C[mi][nt][c] = 0.f;

    stage(0, 0);
    cp_commit();

    for (int c = 0; c < total; c++) {
        const int buf = c & 1;
        if (c + 1 < total) {
            stage(c + 1, buf ^ 1);
            cp_commit();
            cp_wait<1>();
        } else {
            cp_wait<0>();
        }
        __syncthreads();

        const uint32_t aB = aBase0 + buf * bufB;
        const uint32_t bB = bBase0 + buf * bufB;
#pragma unroll
        for (int kk = 0; kk < 4; kk++) {
            const uint32_t kb = kk * 32;
            uint32_t a[2][4];
#pragma unroll
            for (int mi = 0; mi < 2; mi++)
                ldsm4(a[mi][0], a[mi][1], a[mi][2], a[mi][3], aB + aoff[mi] + kb);
            uint32_t b[2][4];
#pragma unroll
            for (int nj = 0; nj < 2; nj++)
                ldsm4(b[nj][0], b[nj][1], b[nj][2], b[nj][3], bB + boff[nj] + kb);
#pragma unroll
            for (int mi = 0; mi < 2; mi++)
#pragma unroll
                for (int nj = 0; nj < 2; nj++) {
                    mma_f16(C[mi][nj * 2 + 0], a[mi], b[nj][0], b[nj][2]);
                    mma_f16(C[mi][nj * 2 + 1], a[mi], b[nj][1], b[nj][3]);
                }
        }
        if (c == scaleAt - 1) {
#pragma unroll
            for (int mi = 0; mi < 2; mi++)
#pragma unroll
                for (int nt = 0; nt < 4; nt++)
#pragma unroll
                    for (int q = 0; q < 4; q++) C[mi][nt][q] *= INVLO;
        }
        __syncthreads();
    }

    // ---- epilogue ----
    const int crow = lane >> 2;
    const int ccol = (lane & 3) * 2;
#pragma unroll
    for (int mi = 0; mi < 2; mi++) {
#pragma unroll
        for (int half = 0; half < 2; half++) {
            const int r = row0 + wm * 32 + mi * 16 + crow + half * 8;
            if (r >= M) continue;
#pragma unroll
            for (int nt = 0; nt < 4; nt++) {
                const int col = col0 + wn * 32 + nt * 8 + ccol;
                float v0 = C[mi][nt][half * 2 + 0];
                float v1 = C[mi][nt][half * 2 + 1];
                v0 += jb.bias1[col];     v1 += jb.bias1[col + 1];
                if (jb.bias2) { v0 += jb.bias2[col]; v1 += jb.bias2[col + 1]; }
                if (jb.act) {
                    v0 = (v0 > 0.f) ? v0 : 0.2f * v0;
                    v1 = (v1 > 0.f) ? v1 : 0.2f * v1;
                }
                if (jb.Cf)
                    *(float2*)(jb.Cf + (size_t)r * DM + col) = make_float2(v0, v1);
                if (jb.Ch) {
                    const h16 h0 = __float2half(v0);
                    const h16 h1 = __float2half(v1);
                    *(__half2*)(jb.Ch + (size_t)r * DM + col) = __halves2half2(h0, h1);
                    if (jb.Cl) {
                        const h16 l0 = __float2half((v0 - __half2float(h0)) * LOSCALE);
                        const h16 l1 = __float2half((v1 - __half2float(h1)) * LOSCALE);
                        *(__half2*)(jb.Cl + (size_t)r * DM + col) = __halves2half2(l0, l1);
                    }
                }
                if (jb.Tth) {   // per-head transposed hi (lo optional): vt[bh][d][s]
                    const h16 h0 = __float2half(v0);
                    const h16 h1 = __float2half(v1);
                    const int bb = r >> 10, s = r & 1023;
                    const int hh = col >> 6, d = col & 63;
                    const size_t base = (((size_t)(bb * HH + hh)) * 64 + d) * 1024 + s;
                    jb.Tth[base] = h0; jb.Tth[base + 1024] = h1;
                    if (jb.Ttl) {
                        const h16 l0 = __float2half((v0 - __half2float(h0)) * LOSCALE);
                        const h16 l1 = __float2half((v1 - __half2float(h1)) * LOSCALE);
                        jb.Ttl[base] = l0; jb.Ttl[base + 1024] = l1;
                    }
                }
            }
        }
    }
}

// ---------------- tensor-core attention (QR=32, fp16; K hi+lo, V hi only) -------
// scores = Qh·Kh + 2^-11·(Qh·Kl'); out = ATh·Vh.
#define QR   32
#define QST  72
#define KST  72
#define VST  136
#define ATST 136
#define SCST 1028
#define KVBUF 18432
#define O_QH   0
#define O_KVH  4608                   // 2 bufs x 18432 (K hi | V hi)
#define O_KVL  41472                  // 2 bufs x 18432 (K lo; unused in V phase)
#define O_ATH  78336                  // 32 x 136 x 2 = 8704
#define O_SC   87040
#define ATT_SMEM (O_SC + QR * SCST * 4)   // 218624

__global__ void __launch_bounds__(512, 1) attn_tc(
    const h16* __restrict__ qph,
    const h16* __restrict__ kph, const h16* __restrict__ kpl,
    const h16* __restrict__ vth,
    const float* __restrict__ mask,
    float* __restrict__ attw, h16* __restrict__ ohh)
{
    extern __shared__ __align__(16) char smem[];
    float* sc = (float*)(smem + O_SC);
    const uint32_t sb = smem_u32(smem);
    const int t = threadIdx.x, w = t >> 5, lane = t & 31;
    const int qt = blockIdx.x, h = blockIdx.y, b = blockIdx.z;
    const int bh = b * HH + h;

    // ---- load Q tile (32x64 hi): 256 uint4 ----
    if (t < 256) {
        const int row = t >> 3, off = (t & 7) * 8;
        const h16* src = qph + ((size_t)(b * SQ + 1 + qt * QR + row)) * DM + h * 64 + off;
        *(uint4*)(smem + O_QH + (row * QST + off) * 2) = *(const uint4*)src;
    }

    auto stage_k = [&](int c, int buf) {
#pragma unroll
        for (int it = 0; it < 4; it++) {
            const int u2 = t + it * 512;
            const int split = u2 >> 10;
            const int u = u2 & 1023;
            const int row = u >> 3, off = (u & 7) * 8;
            const h16* src = (split ? kpl : kph)
                + ((size_t)(b * SQ + c * 128 + row)) * DM + h * 64 + off;
            cp16(sb + (split ? O_KVL : O_KVH) + buf * KVBUF + (row * KST + off) * 2,
                 src, true);
        }
    };
    auto stage_v = [&](int c, int buf) {   // hi only: 1024 cp16 over 512 thr x 2
#pragma unroll
        for (int it = 0; it < 2; it++) {
            const int u = t + it * 512;
            const int row = u >> 4, off = (u & 15) * 8;
            const h16* src = vth + ((size_t)(bh * 64 + row)) * 1024 + c * 128 + off;
            cp16(sb + O_KVH + buf * KVBUF + (row * VST + off) * 2, src, true);
        }
    };

    // ---- score phase: warps (2 row-halves x 8 col-groups), Q hoisted ----
    const int wrow = w >> 3;
    const int wcol = w & 7;
    const int n0s = wcol * 16;

    stage_k(0, 0);
    cp_commit();
    __syncthreads();   // Q visible

    uint32_t qfh[4][4];
#pragma unroll
    for (int kk = 0; kk < 4; kk++) {
        const uint32_t qo = (uint32_t)((wrow * 16 + (lane & 15)) * QST
                            + kk * 16 + ((lane >> 4) << 3)) * 2;
        ldsm4(qfh[kk][0], qfh[kk][1], qfh[kk][2], qfh[kk][3], sb + O_QH + qo);
    }

    const int kg = lane >> 3, kr = lane & 7;
    const uint32_t kobase = (uint32_t)((n0s + ((kg & 1) << 3) + kr) * KST
                            + ((kg >> 1) << 3)) * 2;

    for (int c = 0; c < 8; c++) {
        const int buf = c & 1;
        if (c) __syncthreads();
        if (c + 1 < 8) { stage_k(c + 1, buf ^ 1); cp_commit(); cp_wait<1>(); }
        else           { cp_wait<0>(); }
        __syncthreads();

        float Cm[2][4] = {{0.f,0.f,0.f,0.f},{0.f,0.f,0.f,0.f}};
        float Cc[2][4] = {{0.f,0.f,0.f,0.f},{0.f,0.f,0.f,0.f}};
        const uint32_t kh_base = sb + O_KVH + buf * KVBUF + kobase;
        const uint32_t kl_base = sb + O_KVL + buf * KVBUF + kobase;
#pragma unroll
        for (int kk = 0; kk < 4; kk++) {
            const uint32_t kb = kk * 32;
            uint32_t bh_[4], bl_[4];
            ldsm4(bh_[0], bh_[1], bh_[2], bh_[3], kh_base + kb);
            ldsm4(bl_[0], bl_[1], bl_[2], bl_[3], kl_base + kb);
#pragma unroll
            for (int ng = 0; ng < 2; ng++) {
                mma_f16(Cm[ng], qfh[kk], bh_[ng], bh_[ng + 2]);
                mma_f16(Cc[ng], qfh[kk], bl_[ng], bl_[ng + 2]);
            }
        }
#pragma unroll
        for (int ng = 0; ng < 2; ng++)
#pragma unroll
            for (int half = 0; half < 2; half++) {
                const int row = wrow * 16 + (lane >> 2) + half * 8;
                const int col = c * 128 + n0s + ng * 8 + (lane & 3) * 2;
                const float2 m = *(const float2*)(mask
                    + ((size_t)b * 1024 + qt * QR + row) * 1024 + col);
                const float s0 = Cm[ng][half * 2 + 0] + Cc[ng][half * 2 + 0] * INVLO;
                const float s1 = Cm[ng][half * 2 + 1] + Cc[ng][half * 2 + 1] * INVLO;
                const float v0 = fmaxf(s0 * 0.125f, 0.f) + m.x * (-1e9f);
                const float v1 = fmaxf(s1 * 0.125f, 0.f) + m.y * (-1e9f);
                *(float2*)&sc[row * SCST + col] = make_float2(v0, v1);
            }
    }
    __syncthreads();

    // ---- softmax (warp per 2 rows) + attw write ----
    {
        const size_t abase = (((size_t)b * HH + h) * 1024 + qt * QR) * 1024;
#pragma unroll
        for (int rr = 0; rr < 2; rr++) {
            const int row = w * 2 + rr;
            float* srow = sc + row * SCST;
            float mx = -3.0e38f;
            for (int j = lane; j < 1024; j += 32) mx = fmaxf(mx, srow[j]);
#pragma unroll
            for (int o = 16; o; o >>= 1) mx = fmaxf(mx, __shfl_xor_sync(~0u, mx, o));
            float s = 0.f;
            for (int j = lane; j < 1024; j += 32) {
                const float e = __expf(srow[j] - mx);
                srow[j] = e;
                s += e;
            }
#pragma unroll
            for (int o = 16; o; o >>= 1) s += __shfl_xor_sync(~0u, s, o);
            const float inv = 1.f / s;
            float* arow = attw + abase + (size_t)row * 1024;
            for (int j = lane; j < 1024; j += 32) {
                const float v = srow[j] * inv;
                srow[j] = v;
                arow[j] = v;
            }
        }
    }

    // ---- V phase: out[32,64] = att @ V (hi only); split-k across warp halves ----
    float Om[2][4] = {{0.f,0.f,0.f,0.f},{0.f,0.f,0.f,0.f}};
    const int kko = (w >= 8) ? 4 : 0;
    const int n0v = (w & 7) * 8;
    stage_v(0, 0);
    cp_commit();
    for (int c = 0; c < 8; c++) {
        const int buf = c & 1;
        __syncthreads();
        if (c + 1 < 8) { stage_v(c + 1, buf ^ 1); cp_commit(); }
        // convert att chunk [32x128] fp32 -> fp16 hi (8 elems/thread)
        {
            const int idx = t * 8;
            const int row = idx >> 7, col0 = idx & 127;
            const float* s4 = &sc[row * SCST + c * 128 + col0];
            const float4 f0 = *(const float4*)s4;
            const float4 f1 = *(const float4*)(s4 + 4);
            __half2 ph[4];
            ph[0] = __floats2half2_rn(f0.x, f0.y);
            ph[1] = __floats2half2_rn(f0.z, f0.w);
            ph[2] = __floats2half2_rn(f1.x, f1.y);
            ph[3] = __floats2half2_rn(f1.z, f1.w);
            *(uint4*)(smem + O_ATH + (row * ATST + col0) * 2) = *(uint4*)ph;
        }
        if (c + 1 < 8) cp_wait<1>(); else cp_wait<0>();
        __syncthreads();
#pragma unroll
        for (int kk = 0; kk < 4; kk++) {
            const int kkk = kko + kk;
            uint32_t ah[2][4];
#pragma unroll
            for (int mi = 0; mi < 2; mi++) {
                const uint32_t ao = (uint32_t)((mi * 16 + (lane & 15)) * ATST
                                    + kkk * 16 + ((lane >> 4) << 3)) * 2;
                ldsm4(ah[mi][0], ah[mi][1], ah[mi][2], ah[mi][3], sb + O_ATH + ao);
            }
            const uint32_t vo = (uint32_t)((n0v + (lane & 7)) * VST
                                + kkk * 16 + (((lane >> 3) & 1) << 3)) * 2;
            uint32_t vh0, vh1;
            ldsm2(vh0, vh1, sb + O_KVH + buf * KVBUF + vo);
#pragma unroll
            for (int mi = 0; mi < 2; mi++)
                mma_f16(Om[mi], ah[mi], vh0, vh1);
        }
    }
    // split-k reduction
    __syncthreads();
    float* red = (float*)(smem + O_ATH);
    if (w >= 8) {
        float* dst = red + ((w - 8) * 32 + lane) * 8;
#pragma unroll
        for (int mi = 0; mi < 2; mi++)
#pragma unroll
            for (int i = 0; i < 4; i++) dst[mi * 4 + i] = Om[mi][i];
    }
    __syncthreads();
    if (w < 8) {
        const float* srcp = red + (w * 32 + lane) * 8;
#pragma unroll
        for (int mi = 0; mi < 2; mi++)
#pragma unroll
            for (int half = 0; half < 2; half++) {
                const int r = qt * QR + mi * 16 + (lane >> 2) + half * 8;
                const size_t go = ((size_t)b * 1024 + r) * DM + h * 64 + n0v + (lane & 3) * 2;
                const float v0 = Om[mi][half * 2 + 0] + srcp[mi * 4 + half * 2 + 0];
                const float v1 = Om[mi][half * 2 + 1] + srcp[mi * 4 + half * 2 + 1];
                *(__half2*)(ohh + go) = __floats2half2_rn(v0, v1);
            }
    }
}

// ---------------- launch -------------------------------------------------------
extern "C" void kernel_launch(void* const* d_in, const int* in_sizes, int n_in,
                              void* d_out, int out_size)
{
    const float* q    = (const float*)d_in[0];
    const float* k    = (const float*)d_in[1];
    const float* v    = (const float*)d_in[2];
    const float* e    = (const float*)d_in[3];
    const float* mask = (const float*)d_in[4];
    const float* W[8] = { (const float*)d_in[5],  (const float*)d_in[7],
                          (const float*)d_in[9],  (const float*)d_in[11],
                          (const float*)d_in[13], (const float*)d_in[15],
                          (const float*)d_in[17], (const float*)d_in[19] };
    const float* bq  = (const float*)d_in[6];
    const float* bq2 = (const float*)d_in[8];
    const float* bq3 = (const float*)d_in[10];
    const float* bk  = (const float*)d_in[12];
    const float* bk2 = (const float*)d_in[14];
    const float* bk3 = (const float*)d_in[16];
    const float* bv  = (const float*)d_in[18];
    const float* bo  = (const float*)d_in[20];

    float* out  = (float*)d_out;
    float* attw = out + (size_t)BB * 1024 * DM;

    h16 *Wh, *Wl, *qh, *kh, *eh, *vh, *tqh, *tkh;
    h16 *qph, *kph, *kpl, *vth, *ohh;
    cudaGetSymbolAddress((void**)&Wh,  g_Wh);
    cudaGetSymbolAddress((void**)&Wl,  g_Wl);
    cudaGetSymbolAddress((void**)&qh,  g_qh);
    cudaGetSymbolAddress((void**)&kh,  g_kh);
    cudaGetSymbolAddress((void**)&eh,  g_eh);
    cudaGetSymbolAddress((void**)&vh,  g_vh);
    cudaGetSymbolAddress((void**)&tqh, g_tqh);
    cudaGetSymbolAddress((void**)&tkh, g_tkh);
    cudaGetSymbolAddress((void**)&qph, g_qph);
    cudaGetSymbolAddress((void**)&kph, g_kph); cudaGetSymbolAddress((void**)&kpl, g_kpl);
    cudaGetSymbolAddress((void**)&vth, g_vth);
    cudaGetSymbolAddress((void**)&ohh, g_ohh);

    cudaFuncSetAttribute(gemm_mma, cudaFuncAttributeMaxDynamicSharedMemorySize, GEMM_SMEM);
    cudaFuncSetAttribute(attn_tc,  cudaFuncAttributeMaxDynamicSharedMemorySize, ATT_SMEM);

    {
        CJobs cj;
        cj.j[0] = { q, qh, MQ * DM / 4 };
        cj.j[1] = { k, kh, MQ * DM / 4 };
        cj.j[2] = { e, eh, MQ * DM / 4 };
        cj.j[3] = { v, vh, MV * DM / 4 };
        conv_h_all<<<dim3(256, 1, 4), 256>>>(cj);
    }
    {
        WTJobs wj;
        for (int i = 0; i < 8; i++) wj.W[i] = W[i];
        wj.Th = Wh; wj.Tl = Wl;
        conv_wT_all<<<dim3(32, 32, 8), dim3(32, 8)>>>(wj);
    }

    const size_t WS = (size_t)DM * DM;
    GemmJob jz = {};

    // launch A: t_q, t_k (dual) + vp (hi only, per-head transposed)
    {
        GemmJobs3 g = { { jz, jz, jz } };
        g.j[0] = { qh, Wh + 0 * WS, Wl + 0 * WS, eh, Wh + 1 * WS, Wl + 1 * WS,
                   bq, bq2, nullptr, tqh, nullptr, nullptr, nullptr, MQ, 1 };
        g.j[1] = { kh, Wh + 3 * WS, Wl + 3 * WS, eh, Wh + 4 * WS, Wl + 4 * WS,
                   bk, bk2, nullptr, tkh, nullptr, nullptr, nullptr, MQ, 1 };
        g.j[2] = { vh, Wh + 6 * WS, Wl + 6 * WS, nullptr, nullptr, nullptr,
                   bv, nullptr, nullptr, nullptr, nullptr, vth, nullptr, MV, 0 };
        gemm_mma<<<dim3(8, 33, 3), 512, GEMM_SMEM>>>(g);
    }
    // launch B: qp (hi), kp (hi+lo)
    {
        GemmJobs3 g = { { jz, jz, jz } };
        g.j[0] = { tqh, Wh + 2 * WS, Wl + 2 * WS, nullptr, nullptr, nullptr,
                   bq3, nullptr, nullptr, qph, nullptr, nullptr, nullptr, MQ, 0 };
        g.j[1] = { tkh, Wh + 5 * WS, Wl + 5 * WS, nullptr, nullptr, nullptr,
                   bk3, nullptr, nullptr, kph, kpl, nullptr, nullptr, MQ, 0 };
        gemm_mma<<<dim3(8, 33, 2), 512, GEMM_SMEM>>>(g);
    }

    attn_tc<<<dim3(1024 / QR, HH, BB), 512, ATT_SMEM>>>(
        qph, kph, kpl, vth, mask, attw, ohh);

    // launch C: out = oh @ Wo + bo -> fp32
    {
        GemmJobs3 g = { { jz, jz, jz } };
        g.j[0] = { ohh, Wh + 7 * WS, Wl + 7 * WS, nullptr, nullptr, nullptr,
                   bo, nullptr, out, nullptr, nullptr, nullptr, nullptr, MV, 0 };
        gemm_mma<<<dim3(8, 32, 1), 512, GEMM_SMEM>>>(g);
    }
}

// round 16
// speedup vs baseline: 1.6044x; 1.1140x over previous
#include <cuda_runtime.h>
#include <cuda_fp16.h>
#include <cstdint>

#define DM 1024
#define SQ 1025
#define BB 4
#define HH 16
#define DH 64
#define MQ (BB * SQ)      // 4100
#define MV (BB * 1024)    // 4096
#define LOSCALE 2048.0f
#define INVLO   4.8828125e-4f   // 2^-11

typedef __half h16;

// ---------------- scratch (device globals) ----------------------------------
__device__ __align__(256) h16 g_Wh[8][DM * DM];   // weights [N,K] hi
__device__ __align__(256) h16 g_Wl[8][DM * DM];   // weights lo, pre-scaled x2048
__device__ __align__(256) h16 g_qh[MQ * DM];
__device__ __align__(256) h16 g_kh[MQ * DM];
__device__ __align__(256) h16 g_eh[MQ * DM];
__device__ __align__(256) h16 g_vh[MV * DM];
__device__ __align__(256) h16 g_tqh[MQ * DM];
__device__ __align__(256) h16 g_tkh[MQ * DM];
__device__ __align__(256) h16 g_qph[MQ * DM];
__device__ __align__(256) h16 g_kph[MQ * DM], g_kpl[MQ * DM];   // kp lo scaled
__device__ __align__(256) h16 g_vth[MV * DM];                    // [bh][d][s] hi only
__device__ __align__(256) h16 g_ohh[MV * DM];

// ---------------- PTX helpers -------------------------------------------------
__device__ __forceinline__ uint32_t smem_u32(const void* p) {
    uint32_t a;
    asm("{ .reg .u64 t; cvta.to.shared.u64 t, %1; cvt.u32.u64 %0, t; }"
        : "=r"(a) : "l"(p));
    return a;
}
__device__ __forceinline__ void ldsm4(uint32_t& r0, uint32_t& r1,
                                      uint32_t& r2, uint32_t& r3, uint32_t addr) {
    asm volatile("ldmatrix.sync.aligned.m8n8.x4.shared.b16 {%0,%1,%2,%3}, [%4];"
                 : "=r"(r0), "=r"(r1), "=r"(r2), "=r"(r3) : "r"(addr));
}
__device__ __forceinline__ void ldsm2(uint32_t& r0, uint32_t& r1, uint32_t addr) {
    asm volatile("ldmatrix.sync.aligned.m8n8.x2.shared.b16 {%0,%1}, [%2];"
                 : "=r"(r0), "=r"(r1) : "r"(addr));
}
__device__ __forceinline__ void mma_f16(float* c, const uint32_t* a,
                                        uint32_t b0, uint32_t b1) {
    asm volatile("mma.sync.aligned.m16n8k16.row.col.f32.f16.f16.f32 "
                 "{%0,%1,%2,%3}, {%4,%5,%6,%7}, {%8,%9}, {%0,%1,%2,%3};"
                 : "+f"(c[0]), "+f"(c[1]), "+f"(c[2]), "+f"(c[3])
                 : "r"(a[0]), "r"(a[1]), "r"(a[2]), "r"(a[3]), "r"(b0), "r"(b1));
}
__device__ __forceinline__ void cp16(uint32_t dst, const void* src, bool pred) {
    asm volatile("cp.async.cg.shared.global [%0], [%1], 16, %2;"
                 :: "r"(dst), "l"(src), "r"(pred ? 16u : 0u) : "memory");
}
__device__ __forceinline__ void cp_commit() {
    asm volatile("cp.async.commit_group;" ::: "memory");
}
template <int N>
__device__ __forceinline__ void cp_wait() {
    asm volatile("cp.async.wait_group %0;" :: "n"(N) : "memory");
}

// ---------------- conversion kernels -------------------------------------------
struct CJob  { const float* X; h16* Xh; int n4; };
struct CJobs { CJob j[4]; };

__global__ void conv_h_all(CJobs jobs) {
    const CJob jb = jobs.j[blockIdx.z];
    int i = blockIdx.x * blockDim.x + threadIdx.x;
    const int stride = gridDim.x * blockDim.x;
    for (; i < jb.n4; i += stride) {
        const float4 v = ((const float4*)jb.X)[i];
        ((__half2*)jb.Xh)[2 * i]     = __floats2half2_rn(v.x, v.y);
        ((__half2*)jb.Xh)[2 * i + 1] = __floats2half2_rn(v.z, v.w);
    }
}

struct WTJobs { const float* W[8]; h16* Th; h16* Tl; };

__global__ void conv_wT_all(WTJobs jobs) {
    __shared__ float tile[32][33];
    const float* __restrict__ W = jobs.W[blockIdx.z];
    h16* Th = jobs.Th + (size_t)blockIdx.z * DM * DM;
    h16* Tl = jobs.Tl + (size_t)blockIdx.z * DM * DM;
    const int bx = blockIdx.x * 32, by = blockIdx.y * 32;
    const int tx = threadIdx.x, ty0 = threadIdx.y;
#pragma unroll
    for (int i = 0; i < 4; i++) {
        const int ty = ty0 + i * 8;
        tile[ty][tx] = W[(size_t)(by + ty) * DM + bx + tx];
    }
    __syncthreads();
#pragma unroll
    for (int i = 0; i < 4; i++) {
        const int ty = ty0 + i * 8;
        const float v = tile[tx][ty];
        const h16 h = __float2half(v);
        const h16 l = __float2half((v - __half2float(h)) * LOSCALE);
        Th[(size_t)(bx + ty) * DM + by + tx] = h;
        Tl[(size_t)(bx + ty) * DM + by + tx] = l;
    }
}

// ---------------- batched mma.sync GEMM (fp16, optional lo-correction) ----------
#define ASTG 72
#define GBUF (128 * ASTG)
#define GEMM_SMEM (4 * GBUF * 2)

struct GemmJob {
    const h16 *A0, *B0h, *B0l;    // B0l == nullptr -> no correction for pair 0
    const h16 *A1, *B1h, *B1l;
    const float *bias1, *bias2;
    float *Cf; h16 *Ch, *Cl, *Tth, *Ttl;
    int M, act;
};
struct GemmJobs3 { GemmJob j[3]; };

__global__ void __launch_bounds__(512, 2) gemm_mma(GemmJobs3 jobs)
{
    extern __shared__ __align__(16) h16 dsm[];
    h16* sA = dsm;
    h16* sB = dsm + 2 * GBUF;

    const GemmJob jb = jobs.j[blockIdx.z];
    const int tid  = threadIdx.x;
    const int wid  = tid >> 5;
    const int lane = tid & 31;
    const int wm   = wid & 3;
    const int wn   = wid >> 2;
    const int col0 = blockIdx.x * 128;
    const int row0 = blockIdx.y * 128;
    const int M    = jb.M;
    if (row0 >= M) return;

    // lo segments first (if present), then hi segments
    const h16* segA[4];
    const h16* segB[4];
    int nseg = 0;
    if (jb.B0l)          { segA[nseg] = jb.A0; segB[nseg] = jb.B0l; nseg++; }
    if (jb.A1 && jb.B1l) { segA[nseg] = jb.A1; segB[nseg] = jb.B1l; nseg++; }
    const int nlo = nseg;
    segA[nseg] = jb.A0; segB[nseg] = jb.B0h; nseg++;
    if (jb.A1) { segA[nseg] = jb.A1; segB[nseg] = jb.B1h; nseg++; }
    const int total   = nseg * 16;
    const int scaleAt = nlo * 16;    // 0 -> no scaling needed

    auto stage = [&](int chunk, int buf) {
        const int seg = chunk >> 4;
        const int kc  = (chunk & 15) * 64;
        const h16* __restrict__ A = segA[seg];
        const h16* __restrict__ B = segB[seg];
        const uint32_t dA = smem_u32(sA + buf * GBUF);
        const uint32_t dB = smem_u32(sB + buf * GBUF);
#pragma unroll
        for (int it = 0; it < 2; it++) {
            const int u = tid + it * 512;
            const int row = u >> 3, cg = (u & 7) * 8;
            cp16(dA + (row * ASTG + cg) * 2,
                 A + (size_t)(row0 + row) * DM + kc + cg, row0 + row < M);
            cp16(dB + (row * ASTG + cg) * 2,
                 B + (size_t)(col0 + row) * DM + kc + cg, true);
        }
    };

    uint32_t aoff[2], boff[2];
#pragma unroll
    for (int mi = 0; mi < 2; mi++) {
        const int row = wm * 32 + mi * 16 + (lane & 15);
        aoff[mi] = (uint32_t)(row * ASTG + ((lane >> 4) << 3)) * 2;
    }
    {
        const int g = lane >> 3, r = lane & 7;
#pragma unroll
        for (int nj = 0; nj < 2; nj++) {
            const int row = wn * 32 + nj * 16 + ((g & 1) << 3) + r;
            boff[nj] = (uint32_t)(row * ASTG + ((g >> 1) << 3)) * 2;
        }
    }
    const uint32_t aBase0 = smem_u32(sA);
    const uint32_t bBase0 = smem_u32(sB);
    const uint32_t bufB = (uint32_t)GBUF * 2;

    float C[2][4][4];
#pragma unroll
    for (int mi = 0; mi < 2; mi++)
#pragma unroll
        for (int nt = 0; nt < 4; nt++)
#pragma unroll
            for (int c = 0; c < 4; c++) C[mi][nt][c] = 0.f;

    stage(0, 0);
    cp_commit();

    for (int c = 0; c < total; c++) {
        const int buf = c & 1;
        if (c + 1 < total) {
            stage(c + 1, buf ^ 1);
            cp_commit();
            cp_wait<1>();
        } else {
            cp_wait<0>();
        }
        __syncthreads();

        const uint32_t aB = aBase0 + buf * bufB;
        const uint32_t bB = bBase0 + buf * bufB;
#pragma unroll
        for (int kk = 0; kk < 4; kk++) {
            const uint32_t kb = kk * 32;
            uint32_t a[2][4];
#pragma unroll
            for (int mi = 0; mi < 2; mi++)
                ldsm4(a[mi][0], a[mi][1], a[mi][2], a[mi][3], aB + aoff[mi] + kb);
            uint32_t b[2][4];
#pragma unroll
            for (int nj = 0; nj < 2; nj++)
                ldsm4(b[nj][0], b[nj][1], b[nj][2], b[nj][3], bB + boff[nj] + kb);
#pragma unroll
            for (int mi = 0; mi < 2; mi++)
#pragma unroll
                for (int nj = 0; nj < 2; nj++) {
                    mma_f16(C[mi][nj * 2 + 0], a[mi], b[nj][0], b[nj][2]);
                    mma_f16(C[mi][nj * 2 + 1], a[mi], b[nj][1], b[nj][3]);
                }
        }
        if (scaleAt && c == scaleAt - 1) {   // end of lo segments: C_lo *= 2^-11
#pragma unroll
            for (int mi = 0; mi < 2; mi++)
#pragma unroll
                for (int nt = 0; nt < 4; nt++)
#pragma unroll
                    for (int q = 0; q < 4; q++) C[mi][nt][q] *= INVLO;
        }
        __syncthreads();
    }

    // ---- epilogue ----
    const int crow = lane >> 2;
    const int ccol = (lane & 3) * 2;
#pragma unroll
    for (int mi = 0; mi < 2; mi++) {
#pragma unroll
        for (int half = 0; half < 2; half++) {
            const int r = row0 + wm * 32 + mi * 16 + crow + half * 8;
            if (r >= M) continue;
#pragma unroll
            for (int nt = 0; nt < 4; nt++) {
                const int col = col0 + wn * 32 + nt * 8 + ccol;
                float v0 = C[mi][nt][half * 2 + 0];
                float v1 = C[mi][nt][half * 2 + 1];
                v0 += jb.bias1[col];     v1 += jb.bias1[col + 1];
                if (jb.bias2) { v0 += jb.bias2[col]; v1 += jb.bias2[col + 1]; }
                if (jb.act) {
                    v0 = (v0 > 0.f) ? v0 : 0.2f * v0;
                    v1 = (v1 > 0.f) ? v1 : 0.2f * v1;
                }
                if (jb.Cf)
                    *(float2*)(jb.Cf + (size_t)r * DM + col) = make_float2(v0, v1);
                if (jb.Ch) {
                    const h16 h0 = __float2half(v0);
                    const h16 h1 = __float2half(v1);
                    *(__half2*)(jb.Ch + (size_t)r * DM + col) = __halves2half2(h0, h1);
                    if (jb.Cl) {
                        const h16 l0 = __float2half((v0 - __half2float(h0)) * LOSCALE);
                        const h16 l1 = __float2half((v1 - __half2float(h1)) * LOSCALE);
                        *(__half2*)(jb.Cl + (size_t)r * DM + col) = __halves2half2(l0, l1);
                    }
                }
                if (jb.Tth) {
                    const h16 h0 = __float2half(v0);
                    const h16 h1 = __float2half(v1);
                    const int bb = r >> 10, s = r & 1023;
                    const int hh = col >> 6, d = col & 63;
                    const size_t base = (((size_t)(bb * HH + hh)) * 64 + d) * 1024 + s;
                    jb.Tth[base] = h0; jb.Tth[base + 1024] = h1;
                    if (jb.Ttl) {
                        const h16 l0 = __float2half((v0 - __half2float(h0)) * LOSCALE);
                        const h16 l1 = __float2half((v1 - __half2float(h1)) * LOSCALE);
                        jb.Ttl[base] = l0; jb.Ttl[base + 1024] = l1;
                    }
                }
            }
        }
    }
}

// ---------------- tensor-core attention (QR=32, fp16; K hi+lo, V hi only) -------
#define QR   32
#define QST  72
#define KST  72
#define VST  136
#define ATST 136
#define SCST 1028
#define KVBUF 18432
#define O_QH   0
#define O_KVH  4608
#define O_KVL  41472
#define O_ATH  78336
#define O_SC   87040
#define ATT_SMEM (O_SC + QR * SCST * 4)   // 218624

__global__ void __launch_bounds__(512, 1) attn_tc(
    const h16* __restrict__ qph,
    const h16* __restrict__ kph, const h16* __restrict__ kpl,
    const h16* __restrict__ vth,
    const float* __restrict__ mask,
    float* __restrict__ attw, h16* __restrict__ ohh)
{
    extern __shared__ __align__(16) char smem[];
    float* sc = (float*)(smem + O_SC);
    const uint32_t sb = smem_u32(smem);
    const int t = threadIdx.x, w = t >> 5, lane = t & 31;
    const int qt = blockIdx.x, h = blockIdx.y, b = blockIdx.z;
    const int bh = b * HH + h;

    if (t < 256) {
        const int row = t >> 3, off = (t & 7) * 8;
        const h16* src = qph + ((size_t)(b * SQ + 1 + qt * QR + row)) * DM + h * 64 + off;
        *(uint4*)(smem + O_QH + (row * QST + off) * 2) = *(const uint4*)src;
    }

    auto stage_k = [&](int c, int buf) {
#pragma unroll
        for (int it = 0; it < 4; it++) {
            const int u2 = t + it * 512;
            const int split = u2 >> 10;
            const int u = u2 & 1023;
            const int row = u >> 3, off = (u & 7) * 8;
            const h16* src = (split ? kpl : kph)
                + ((size_t)(b * SQ + c * 128 + row)) * DM + h * 64 + off;
            cp16(sb + (split ? O_KVL : O_KVH) + buf * KVBUF + (row * KST + off) * 2,
                 src, true);
        }
    };
    auto stage_v = [&](int c, int buf) {
#pragma unroll
        for (int it = 0; it < 2; it++) {
            const int u = t + it * 512;
            const int row = u >> 4, off = (u & 15) * 8;
            const h16* src = vth + ((size_t)(bh * 64 + row)) * 1024 + c * 128 + off;
            cp16(sb + O_KVH + buf * KVBUF + (row * VST + off) * 2, src, true);
        }
    };

    const int wrow = w >> 3;
    const int wcol = w & 7;
    const int n0s = wcol * 16;

    stage_k(0, 0);
    cp_commit();
    __syncthreads();

    uint32_t qfh[4][4];
#pragma unroll
    for (int kk = 0; kk < 4; kk++) {
        const uint32_t qo = (uint32_t)((wrow * 16 + (lane & 15)) * QST
                            + kk * 16 + ((lane >> 4) << 3)) * 2;
        ldsm4(qfh[kk][0], qfh[kk][1], qfh[kk][2], qfh[kk][3], sb + O_QH + qo);
    }

    const int kg = lane >> 3, kr = lane & 7;
    const uint32_t kobase = (uint32_t)((n0s + ((kg & 1) << 3) + kr) * KST
                            + ((kg >> 1) << 3)) * 2;

    for (int c = 0; c < 8; c++) {
        const int buf = c & 1;
        if (c) __syncthreads();
        if (c + 1 < 8) { stage_k(c + 1, buf ^ 1); cp_commit(); cp_wait<1>(); }
        else           { cp_wait<0>(); }
        __syncthreads();

        float Cm[2][4] = {{0.f,0.f,0.f,0.f},{0.f,0.f,0.f,0.f}};
        float Cc[2][4] = {{0.f,0.f,0.f,0.f},{0.f,0.f,0.f,0.f}};
        const uint32_t kh_base = sb + O_KVH + buf * KVBUF + kobase;
        const uint32_t kl_base = sb + O_KVL + buf * KVBUF + kobase;
#pragma unroll
        for (int kk = 0; kk < 4; kk++) {
            const uint32_t kb = kk * 32;
            uint32_t bh_[4], bl_[4];
            ldsm4(bh_[0], bh_[1], bh_[2], bh_[3], kh_base + kb);
            ldsm4(bl_[0], bl_[1], bl_[2], bl_[3], kl_base + kb);
#pragma unroll
            for (int ng = 0; ng < 2; ng++) {
                mma_f16(Cm[ng], qfh[kk], bh_[ng], bh_[ng + 2]);
                mma_f16(Cc[ng], qfh[kk], bl_[ng], bl_[ng + 2]);
            }
        }
#pragma unroll
        for (int ng = 0; ng < 2; ng++)
#pragma unroll
            for (int half = 0; half < 2; half++) {
                const int row = wrow * 16 + (lane >> 2) + half * 8;
                const int col = c * 128 + n0s + ng * 8 + (lane & 3) * 2;
                const float2 m = *(const float2*)(mask
                    + ((size_t)b * 1024 + qt * QR + row) * 1024 + col);
                const float s0 = Cm[ng][half * 2 + 0] + Cc[ng][half * 2 + 0] * INVLO;
                const float s1 = Cm[ng][half * 2 + 1] + Cc[ng][half * 2 + 1] * INVLO;
                const float v0 = fmaxf(s0 * 0.125f, 0.f) + m.x * (-1e9f);
                const float v1 = fmaxf(s1 * 0.125f, 0.f) + m.y * (-1e9f);
                *(float2*)&sc[row * SCST + col] = make_float2(v0, v1);
            }
    }
    __syncthreads();

    // ---- softmax (warp per 2 rows) + attw write ----
    {
        const size_t abase = (((size_t)b * HH + h) * 1024 + qt * QR) * 1024;
#pragma unroll
        for (int rr = 0; rr < 2; rr++) {
            const int row = w * 2 + rr;
            float* srow = sc + row * SCST;
            float mx = -3.0e38f;
            for (int j = lane; j < 1024; j += 32) mx = fmaxf(mx, srow[j]);
#pragma unroll
            for (int o = 16; o; o >>= 1) mx = fmaxf(mx, __shfl_xor_sync(~0u, mx, o));
            float s = 0.f;
            for (int j = lane; j < 1024; j += 32) {
                const float e = __expf(srow[j] - mx);
                srow[j] = e;
                s += e;
            }
#pragma unroll
            for (int o = 16; o; o >>= 1) s += __shfl_xor_sync(~0u, s, o);
            const float inv = 1.f / s;
            float* arow = attw + abase + (size_t)row * 1024;
            for (int j = lane; j < 1024; j += 32) {
                const float v = srow[j] * inv;
                srow[j] = v;
                arow[j] = v;
            }
        }
    }

    // ---- V phase ----
    float Om[2][4] = {{0.f,0.f,0.f,0.f},{0.f,0.f,0.f,0.f}};
    const int kko = (w >= 8) ? 4 : 0;
    const int n0v = (w & 7) * 8;
    stage_v(0, 0);
    cp_commit();
    for (int c = 0; c < 8; c++) {
        const int buf = c & 1;
        __syncthreads();
        if (c + 1 < 8) { stage_v(c + 1, buf ^ 1); cp_commit(); }
        {
            const int idx = t * 8;
            const int row = idx >> 7, col0 = idx & 127;
            const float* s4 = &sc[row * SCST + c * 128 + col0];
            const float4 f0 = *(const float4*)s4;
            const float4 f1 = *(const float4*)(s4 + 4);
            __half2 ph[4];
            ph[0] = __floats2half2_rn(f0.x, f0.y);
            ph[1] = __floats2half2_rn(f0.z, f0.w);
            ph[2] = __floats2half2_rn(f1.x, f1.y);
            ph[3] = __floats2half2_rn(f1.z, f1.w);
            *(uint4*)(smem + O_ATH + (row * ATST + col0) * 2) = *(uint4*)ph;
        }
        if (c + 1 < 8) cp_wait<1>(); else cp_wait<0>();
        __syncthreads();
#pragma unroll
        for (int kk = 0; kk < 4; kk++) {
            const int kkk = kko + kk;
            uint32_t ah[2][4];
#pragma unroll
            for (int mi = 0; mi < 2; mi++) {
                const uint32_t ao = (uint32_t)((mi * 16 + (lane & 15)) * ATST
                                    + kkk * 16 + ((lane >> 4) << 3)) * 2;
                ldsm4(ah[mi][0], ah[mi][1], ah[mi][2], ah[mi][3], sb + O_ATH + ao);
            }
            const uint32_t vo = (uint32_t)((n0v + (lane & 7)) * VST
                                + kkk * 16 + (((lane >> 3) & 1) << 3)) * 2;
            uint32_t vh0, vh1;
            ldsm2(vh0, vh1, sb + O_KVH + buf * KVBUF + vo);
#pragma unroll
            for (int mi = 0; mi < 2; mi++)
                mma_f16(Om[mi], ah[mi], vh0, vh1);
        }
    }
    __syncthreads();
    float* red = (float*)(smem + O_ATH);
    if (w >= 8) {
        float* dst = red + ((w - 8) * 32 + lane) * 8;
#pragma unroll
        for (int mi = 0; mi < 2; mi++)
#pragma unroll
            for (int i = 0; i < 4; i++) dst[mi * 4 + i] = Om[mi][i];
    }
    __syncthreads();
    if (w < 8) {
        const float* srcp = red + (w * 32 + lane) * 8;
#pragma unroll
        for (int mi = 0; mi < 2; mi++)
#pragma unroll
            for (int half = 0; half < 2; half++) {
                const int r = qt * QR + mi * 16 + (lane >> 2) + half * 8;
                const size_t go = ((size_t)b * 1024 + r) * DM + h * 64 + n0v + (lane & 3) * 2;
                const float v0 = Om[mi][half * 2 + 0] + srcp[mi * 4 + half * 2 + 0];
                const float v1 = Om[mi][half * 2 + 1] + srcp[mi * 4 + half * 2 + 1];
                *(__half2*)(ohh + go) = __floats2half2_rn(v0, v1);
            }
    }
}

// ---------------- launch -------------------------------------------------------
extern "C" void kernel_launch(void* const* d_in, const int* in_sizes, int n_in,
                              void* d_out, int out_size)
{
    const float* q    = (const float*)d_in[0];
    const float* k    = (const float*)d_in[1];
    const float* v    = (const float*)d_in[2];
    const float* e    = (const float*)d_in[3];
    const float* mask = (const float*)d_in[4];
    const float* W[8] = { (const float*)d_in[5],  (const float*)d_in[7],
                          (const float*)d_in[9],  (const float*)d_in[11],
                          (const float*)d_in[13], (const float*)d_in[15],
                          (const float*)d_in[17], (const float*)d_in[19] };
    const float* bq  = (const float*)d_in[6];
    const float* bq2 = (const float*)d_in[8];
    const float* bq3 = (const float*)d_in[10];
    const float* bk  = (const float*)d_in[12];
    const float* bk2 = (const float*)d_in[14];
    const float* bk3 = (const float*)d_in[16];
    const float* bv  = (const float*)d_in[18];
    const float* bo  = (const float*)d_in[20];

    float* out  = (float*)d_out;
    float* attw = out + (size_t)BB * 1024 * DM;

    h16 *Wh, *Wl, *qh, *kh, *eh, *vh, *tqh, *tkh;
    h16 *qph, *kph, *kpl, *vth, *ohh;
    cudaGetSymbolAddress((void**)&Wh,  g_Wh);
    cudaGetSymbolAddress((void**)&Wl,  g_Wl);
    cudaGetSymbolAddress((void**)&qh,  g_qh);
    cudaGetSymbolAddress((void**)&kh,  g_kh);
    cudaGetSymbolAddress((void**)&eh,  g_eh);
    cudaGetSymbolAddress((void**)&vh,  g_vh);
    cudaGetSymbolAddress((void**)&tqh, g_tqh);
    cudaGetSymbolAddress((void**)&tkh, g_tkh);
    cudaGetSymbolAddress((void**)&qph, g_qph);
    cudaGetSymbolAddress((void**)&kph, g_kph); cudaGetSymbolAddress((void**)&kpl, g_kpl);
    cudaGetSymbolAddress((void**)&vth, g_vth);
    cudaGetSymbolAddress((void**)&ohh, g_ohh);

    cudaFuncSetAttribute(gemm_mma, cudaFuncAttributeMaxDynamicSharedMemorySize, GEMM_SMEM);
    cudaFuncSetAttribute(attn_tc,  cudaFuncAttributeMaxDynamicSharedMemorySize, ATT_SMEM);

    {
        CJobs cj;
        cj.j[0] = { q, qh, MQ * DM / 4 };
        cj.j[1] = { k, kh, MQ * DM / 4 };
        cj.j[2] = { e, eh, MQ * DM / 4 };
        cj.j[3] = { v, vh, MV * DM / 4 };
        conv_h_all<<<dim3(256, 1, 4), 256>>>(cj);
    }
    {
        WTJobs wj;
        for (int i = 0; i < 8; i++) wj.W[i] = W[i];
        wj.Th = Wh; wj.Tl = Wl;
        conv_wT_all<<<dim3(32, 32, 8), dim3(32, 8)>>>(wj);
    }

    const size_t WS = (size_t)DM * DM;
    GemmJob jz = {};

    // launch A: t_q, t_k (dual, W hi-only) + vp (2-term W)  — all 32 chunks/CTA
    {
        GemmJobs3 g = { { jz, jz, jz } };
        g.j[0] = { qh, Wh + 0 * WS, nullptr, eh, Wh + 1 * WS, nullptr,
                   bq, bq2, nullptr, tqh, nullptr, nullptr, nullptr, MQ, 1 };
        g.j[1] = { kh, Wh + 3 * WS, nullptr, eh, Wh + 4 * WS, nullptr,
                   bk, bk2, nullptr, tkh, nullptr, nullptr, nullptr, MQ, 1 };
        g.j[2] = { vh, Wh + 6 * WS, Wl + 6 * WS, nullptr, nullptr, nullptr,
                   bv, nullptr, nullptr, nullptr, nullptr, vth, nullptr, MV, 0 };
        gemm_mma<<<dim3(8, 33, 3), 512, GEMM_SMEM>>>(g);
    }
    // launch B: qp (hi out, 2-term W), kp (hi+lo out, 2-term W)
    {
        GemmJobs3 g = { { jz, jz, jz } };
        g.j[0] = { tqh, Wh + 2 * WS, Wl + 2 * WS, nullptr, nullptr, nullptr,
                   bq3, nullptr, nullptr, qph, nullptr, nullptr, nullptr, MQ, 0 };
        g.j[1] = { tkh, Wh + 5 * WS, Wl + 5 * WS, nullptr, nullptr, nullptr,
                   bk3, nullptr, nullptr, kph, kpl, nullptr, nullptr, MQ, 0 };
        gemm_mma<<<dim3(8, 33, 2), 512, GEMM_SMEM>>>(g);
    }

    attn_tc<<<dim3(1024 / QR, HH, BB), 512, ATT_SMEM>>>(
        qph, kph, kpl, vth, mask, attw, ohh);

    // launch C: out = oh @ Wo + bo (2-term W) -> fp32
    {
        GemmJobs3 g = { { jz, jz, jz } };
        g.j[0] = { ohh, Wh + 7 * WS, Wl + 7 * WS, nullptr, nullptr, nullptr,
                   bo, nullptr, out, nullptr, nullptr, nullptr, nullptr, MV, 0 };
        gemm_mma<<<dim3(8, 32, 1), 512, GEMM_SMEM>>>(g);
    }
}

// round 17
// speedup vs baseline: 2.0001x; 1.2466x over previous
#include <cuda_runtime.h>
#include <cuda_fp16.h>
#include <cstdint>

#define DM 1024
#define SQ 1025
#define BB 4
#define HH 16
#define DH 64
#define MQ (BB * SQ)      // 4100
#define MV (BB * 1024)    // 4096
#define LOSCALE 2048.0f
#define INVLO   4.8828125e-4f   // 2^-11

typedef __half h16;

// ---------------- scratch (device globals) ----------------------------------
__device__ __align__(256) h16 g_Wh[8][DM * DM];   // weights [N,K] hi
__device__ __align__(256) h16 g_qh[MQ * DM];
__device__ __align__(256) h16 g_kh[MQ * DM];
__device__ __align__(256) h16 g_eh[MQ * DM];
__device__ __align__(256) h16 g_vh[MV * DM];
__device__ __align__(256) h16 g_tqh[MQ * DM];
__device__ __align__(256) h16 g_tkh[MQ * DM];
__device__ __align__(256) h16 g_qph[MQ * DM];
__device__ __align__(256) h16 g_kph[MQ * DM], g_kpl[MQ * DM];   // kp lo scaled
__device__ __align__(256) h16 g_vth[MV * DM];                    // [bh][d][s] hi only
__device__ __align__(256) h16 g_ohh[MV * DM];

// ---------------- PTX helpers -------------------------------------------------
__device__ __forceinline__ uint32_t smem_u32(const void* p) {
    uint32_t a;
    asm("{ .reg .u64 t; cvta.to.shared.u64 t, %1; cvt.u32.u64 %0, t; }"
        : "=r"(a) : "l"(p));
    return a;
}
__device__ __forceinline__ void ldsm4(uint32_t& r0, uint32_t& r1,
                                      uint32_t& r2, uint32_t& r3, uint32_t addr) {
    asm volatile("ldmatrix.sync.aligned.m8n8.x4.shared.b16 {%0,%1,%2,%3}, [%4];"
                 : "=r"(r0), "=r"(r1), "=r"(r2), "=r"(r3) : "r"(addr));
}
__device__ __forceinline__ void ldsm2(uint32_t& r0, uint32_t& r1, uint32_t addr) {
    asm volatile("ldmatrix.sync.aligned.m8n8.x2.shared.b16 {%0,%1}, [%2];"
                 : "=r"(r0), "=r"(r1) : "r"(addr));
}
__device__ __forceinline__ void mma_f16(float* c, const uint32_t* a,
                                        uint32_t b0, uint32_t b1) {
    asm volatile("mma.sync.aligned.m16n8k16.row.col.f32.f16.f16.f32 "
                 "{%0,%1,%2,%3}, {%4,%5,%6,%7}, {%8,%9}, {%0,%1,%2,%3};"
                 : "+f"(c[0]), "+f"(c[1]), "+f"(c[2]), "+f"(c[3])
                 : "r"(a[0]), "r"(a[1]), "r"(a[2]), "r"(a[3]), "r"(b0), "r"(b1));
}
__device__ __forceinline__ void cp16(uint32_t dst, const void* src, bool pred) {
    asm volatile("cp.async.cg.shared.global [%0], [%1], 16, %2;"
                 :: "r"(dst), "l"(src), "r"(pred ? 16u : 0u) : "memory");
}
__device__ __forceinline__ void cp_commit() {
    asm volatile("cp.async.commit_group;" ::: "memory");
}
template <int N>
__device__ __forceinline__ void cp_wait() {
    asm volatile("cp.async.wait_group %0;" :: "n"(N) : "memory");
}

// ---------------- conversion kernels -------------------------------------------
struct CJob  { const float* X; h16* Xh; int n4; };
struct CJobs { CJob j[4]; };

__global__ void conv_h_all(CJobs jobs) {
    const CJob jb = jobs.j[blockIdx.z];
    int i = blockIdx.x * blockDim.x + threadIdx.x;
    const int stride = gridDim.x * blockDim.x;
    for (; i < jb.n4; i += stride) {
        const float4 v = ((const float4*)jb.X)[i];
        ((__half2*)jb.Xh)[2 * i]     = __floats2half2_rn(v.x, v.y);
        ((__half2*)jb.Xh)[2 * i + 1] = __floats2half2_rn(v.z, v.w);
    }
}

struct WTJobs { const float* W[8]; h16* Th; };

__global__ void conv_wT_all(WTJobs jobs) {
    __shared__ float tile[32][33];
    const float* __restrict__ W = jobs.W[blockIdx.z];
    h16* Th = jobs.Th + (size_t)blockIdx.z * DM * DM;
    const int bx = blockIdx.x * 32, by = blockIdx.y * 32;
    const int tx = threadIdx.x, ty0 = threadIdx.y;
#pragma unroll
    for (int i = 0; i < 4; i++) {
        const int ty = ty0 + i * 8;
        tile[ty][tx] = W[(size_t)(by + ty) * DM + bx + tx];
    }
    __syncthreads();
#pragma unroll
    for (int i = 0; i < 4; i++) {
        const int ty = ty0 + i * 8;
        Th[(size_t)(bx + ty) * DM + by + tx] = __float2half(tile[tx][ty]);
    }
}

// ---------------- batched mma.sync GEMM (fp16 hi-only weights) ------------------
#define ASTG 72
#define GBUF (128 * ASTG)
#define GEMM_SMEM (4 * GBUF * 2)

struct GemmJob {
    const h16 *A0, *B0h;
    const h16 *A1, *B1h;
    const float *bias1, *bias2;
    float *Cf; h16 *Ch, *Cl, *Tth;
    int M, act;
};
struct GemmJobs3 { GemmJob j[3]; };

__global__ void __launch_bounds__(512, 2) gemm_mma(GemmJobs3 jobs)
{
    extern __shared__ __align__(16) h16 dsm[];
    h16* sA = dsm;
    h16* sB = dsm + 2 * GBUF;

    const GemmJob jb = jobs.j[blockIdx.z];
    const int tid  = threadIdx.x;
    const int wid  = tid >> 5;
    const int lane = tid & 31;
    const int wm   = wid & 3;
    const int wn   = wid >> 2;
    const int col0 = blockIdx.x * 128;
    const int row0 = blockIdx.y * 128;
    const int M    = jb.M;
    if (row0 >= M) return;

    const h16* segA[2];
    const h16* segB[2];
    segA[0] = jb.A0; segB[0] = jb.B0h;
    int nseg = 1;
    if (jb.A1) { segA[1] = jb.A1; segB[1] = jb.B1h; nseg = 2; }
    const int total = nseg * 16;

    auto stage = [&](int chunk, int buf) {
        const int seg = chunk >> 4;
        const int kc  = (chunk & 15) * 64;
        const h16* __restrict__ A = segA[seg];
        const h16* __restrict__ B = segB[seg];
        const uint32_t dA = smem_u32(sA + buf * GBUF);
        const uint32_t dB = smem_u32(sB + buf * GBUF);
#pragma unroll
        for (int it = 0; it < 2; it++) {
            const int u = tid + it * 512;
            const int row = u >> 3, cg = (u & 7) * 8;
            cp16(dA + (row * ASTG + cg) * 2,
                 A + (size_t)(row0 + row) * DM + kc + cg, row0 + row < M);
            cp16(dB + (row * ASTG + cg) * 2,
                 B + (size_t)(col0 + row) * DM + kc + cg, true);
        }
    };

    uint32_t aoff[2], boff[2];
#pragma unroll
    for (int mi = 0; mi < 2; mi++) {
        const int row = wm * 32 + mi * 16 + (lane & 15);
        aoff[mi] = (uint32_t)(row * ASTG + ((lane >> 4) << 3)) * 2;
    }
    {
        const int g = lane >> 3, r = lane & 7;
#pragma unroll
        for (int nj = 0; nj < 2; nj++) {
            const int row = wn * 32 + nj * 16 + ((g & 1) << 3) + r;
            boff[nj] = (uint32_t)(row * ASTG + ((g >> 1) << 3)) * 2;
        }
    }
    const uint32_t aBase0 = smem_u32(sA);
    const uint32_t bBase0 = smem_u32(sB);
    const uint32_t bufB = (uint32_t)GBUF * 2;

    float C[2][4][4];
#pragma unroll
    for (int mi = 0; mi < 2; mi++)
#pragma unroll
        for (int nt = 0; nt < 4; nt++)
#pragma unroll
            for (int c = 0; c < 4; c++) C[mi][nt][c] = 0.f;

    stage(0, 0);
    cp_commit();

    for (int c = 0; c < total; c++) {
        const int buf = c & 1;
        if (c + 1 < total) {
            stage(c + 1, buf ^ 1);
            cp_commit();
            cp_wait<1>();
        } else {
            cp_wait<0>();
        }
        __syncthreads();

        const uint32_t aB = aBase0 + buf * bufB;
        const uint32_t bB = bBase0 + buf * bufB;
#pragma unroll
        for (int kk = 0; kk < 4; kk++) {
            const uint32_t kb = kk * 32;
            uint32_t a[2][4];
#pragma unroll
            for (int mi = 0; mi < 2; mi++)
                ldsm4(a[mi][0], a[mi][1], a[mi][2], a[mi][3], aB + aoff[mi] + kb);
            uint32_t b[2][4];
#pragma unroll
            for (int nj = 0; nj < 2; nj++)
                ldsm4(b[nj][0], b[nj][1], b[nj][2], b[nj][3], bB + boff[nj] + kb);
#pragma unroll
            for (int mi = 0; mi < 2; mi++)
#pragma unroll
                for (int nj = 0; nj < 2; nj++) {
                    mma_f16(C[mi][nj * 2 + 0], a[mi], b[nj][0], b[nj][2]);
                    mma_f16(C[mi][nj * 2 + 1], a[mi], b[nj][1], b[nj][3]);
                }
        }
        __syncthreads();
    }

    // ---- epilogue ----
    const int crow = lane >> 2;
    const int ccol = (lane & 3) * 2;
#pragma unroll
    for (int mi = 0; mi < 2; mi++) {
#pragma unroll
        for (int half = 0; half < 2; half++) {
            const int r = row0 + wm * 32 + mi * 16 + crow + half * 8;
            if (r >= M) continue;
#pragma unroll
            for (int nt = 0; nt < 4; nt++) {
                const int col = col0 + wn * 32 + nt * 8 + ccol;
                float v0 = C[mi][nt][half * 2 + 0];
                float v1 = C[mi][nt][half * 2 + 1];
                v0 += jb.bias1[col];     v1 += jb.bias1[col + 1];
                if (jb.bias2) { v0 += jb.bias2[col]; v1 += jb.bias2[col + 1]; }
                if (jb.act) {
                    v0 = (v0 > 0.f) ? v0 : 0.2f * v0;
                    v1 = (v1 > 0.f) ? v1 : 0.2f * v1;
                }
                if (jb.Cf)
                    *(float2*)(jb.Cf + (size_t)r * DM + col) = make_float2(v0, v1);
                if (jb.Ch) {
                    const h16 h0 = __float2half(v0);
                    const h16 h1 = __float2half(v1);
                    *(__half2*)(jb.Ch + (size_t)r * DM + col) = __halves2half2(h0, h1);
                    if (jb.Cl) {
                        const h16 l0 = __float2half((v0 - __half2float(h0)) * LOSCALE);
                        const h16 l1 = __float2half((v1 - __half2float(h1)) * LOSCALE);
                        *(__half2*)(jb.Cl + (size_t)r * DM + col) = __halves2half2(l0, l1);
                    }
                }
                if (jb.Tth) {
                    const h16 h0 = __float2half(v0);
                    const h16 h1 = __float2half(v1);
                    const int bb = r >> 10, s = r & 1023;
                    const int hh = col >> 6, d = col & 63;
                    const size_t base = (((size_t)(bb * HH + hh)) * 64 + d) * 1024 + s;
                    jb.Tth[base] = h0; jb.Tth[base + 1024] = h1;
                }
            }
        }
    }
}

// ---------------- tensor-core attention (QR=32, fp16; K hi+lo, V hi only) -------
#define QR   32
#define QST  72
#define KST  72
#define VST  136
#define ATST 136
#define SCST 1028
#define KVBUF 18432
#define O_QH   0
#define O_KVH  4608
#define O_KVL  41472
#define O_ATH  78336
#define O_SC   87040
#define ATT_SMEM (O_SC + QR * SCST * 4)   // 218624

__global__ void __launch_bounds__(512, 1) attn_tc(
    const h16* __restrict__ qph,
    const h16* __restrict__ kph, const h16* __restrict__ kpl,
    const h16* __restrict__ vth,
    const float* __restrict__ mask,
    float* __restrict__ attw, h16* __restrict__ ohh)
{
    extern __shared__ __align__(16) char smem[];
    float* sc = (float*)(smem + O_SC);
    const uint32_t sb = smem_u32(smem);
    const int t = threadIdx.x, w = t >> 5, lane = t & 31;
    const int qt = blockIdx.x, h = blockIdx.y, b = blockIdx.z;
    const int bh = b * HH + h;

    if (t < 256) {
        const int row = t >> 3, off = (t & 7) * 8;
        const h16* src = qph + ((size_t)(b * SQ + 1 + qt * QR + row)) * DM + h * 64 + off;
        *(uint4*)(smem + O_QH + (row * QST + off) * 2) = *(const uint4*)src;
    }

    auto stage_k = [&](int c, int buf) {
#pragma unroll
        for (int it = 0; it < 4; it++) {
            const int u2 = t + it * 512;
            const int split = u2 >> 10;
            const int u = u2 & 1023;
            const int row = u >> 3, off = (u & 7) * 8;
            const h16* src = (split ? kpl : kph)
                + ((size_t)(b * SQ + c * 128 + row)) * DM + h * 64 + off;
            cp16(sb + (split ? O_KVL : O_KVH) + buf * KVBUF + (row * KST + off) * 2,
                 src, true);
        }
    };
    auto stage_v = [&](int c, int buf) {
#pragma unroll
        for (int it = 0; it < 2; it++) {
            const int u = t + it * 512;
            const int row = u >> 4, off = (u & 15) * 8;
            const h16* src = vth + ((size_t)(bh * 64 + row)) * 1024 + c * 128 + off;
            cp16(sb + O_KVH + buf * KVBUF + (row * VST + off) * 2, src, true);
        }
    };

    const int wrow = w >> 3;
    const int wcol = w & 7;
    const int n0s = wcol * 16;

    stage_k(0, 0);
    cp_commit();
    __syncthreads();

    uint32_t qfh[4][4];
#pragma unroll
    for (int kk = 0; kk < 4; kk++) {
        const uint32_t qo = (uint32_t)((wrow * 16 + (lane & 15)) * QST
                            + kk * 16 + ((lane >> 4) << 3)) * 2;
        ldsm4(qfh[kk][0], qfh[kk][1], qfh[kk][2], qfh[kk][3], sb + O_QH + qo);
    }

    const int kg = lane >> 3, kr = lane & 7;
    const uint32_t kobase = (uint32_t)((n0s + ((kg & 1) << 3) + kr) * KST
                            + ((kg >> 1) << 3)) * 2;

    for (int c = 0; c < 8; c++) {
        const int buf = c & 1;
        if (c) __syncthreads();
        if (c + 1 < 8) { stage_k(c + 1, buf ^ 1); cp_commit(); cp_wait<1>(); }
        else           { cp_wait<0>(); }
        __syncthreads();

        float Cm[2][4] = {{0.f,0.f,0.f,0.f},{0.f,0.f,0.f,0.f}};
        float Cc[2][4] = {{0.f,0.f,0.f,0.f},{0.f,0.f,0.f,0.f}};
        const uint32_t kh_base = sb + O_KVH + buf * KVBUF + kobase;
        const uint32_t kl_base = sb + O_KVL + buf * KVBUF + kobase;
#pragma unroll
        for (int kk = 0; kk < 4; kk++) {
            const uint32_t kb = kk * 32;
            uint32_t bh_[4], bl_[4];
            ldsm4(bh_[0], bh_[1], bh_[2], bh_[3], kh_base + kb);
            ldsm4(bl_[0], bl_[1], bl_[2], bl_[3], kl_base + kb);
#pragma unroll
            for (int ng = 0; ng < 2; ng++) {
                mma_f16(Cm[ng], qfh[kk], bh_[ng], bh_[ng + 2]);
                mma_f16(Cc[ng], qfh[kk], bl_[ng], bl_[ng + 2]);
            }
        }
#pragma unroll
        for (int ng = 0; ng < 2; ng++)
#pragma unroll
            for (int half = 0; half < 2; half++) {
                const int row = wrow * 16 + (lane >> 2) + half * 8;
                const int col = c * 128 + n0s + ng * 8 + (lane & 3) * 2;
                const float2 m = *(const float2*)(mask
                    + ((size_t)b * 1024 + qt * QR + row) * 1024 + col);
                const float s0 = Cm[ng][half * 2 + 0] + Cc[ng][half * 2 + 0] * INVLO;
                const float s1 = Cm[ng][half * 2 + 1] + Cc[ng][half * 2 + 1] * INVLO;
                const float v0 = fmaxf(s0 * 0.125f, 0.f) + m.x * (-1e9f);
                const float v1 = fmaxf(s1 * 0.125f, 0.f) + m.y * (-1e9f);
                *(float2*)&sc[row * SCST + col] = make_float2(v0, v1);
            }
    }
    __syncthreads();

    // ---- softmax (warp per 2 rows) + attw write ----
    {
        const size_t abase = (((size_t)b * HH + h) * 1024 + qt * QR) * 1024;
#pragma unroll
        for (int rr = 0; rr < 2; rr++) {
            const int row = w * 2 + rr;
            float* srow = sc + row * SCST;
            float mx = -3.0e38f;
            for (int j = lane; j < 1024; j += 32) mx = fmaxf(mx, srow[j]);
#pragma unroll
            for (int o = 16; o; o >>= 1) mx = fmaxf(mx, __shfl_xor_sync(~0u, mx, o));
            float s = 0.f;
            for (int j = lane; j < 1024; j += 32) {
                const float e = __expf(srow[j] - mx);
                srow[j] = e;
                s += e;
            }
#pragma unroll
            for (int o = 16; o; o >>= 1) s += __shfl_xor_sync(~0u, s, o);
            const float inv = 1.f / s;
            float* arow = attw + abase + (size_t)row * 1024;
            for (int j = lane; j < 1024; j += 32) {
                const float v = srow[j] * inv;
                srow[j] = v;
                arow[j] = v;
            }
        }
    }

    // ---- V phase ----
    float Om[2][4] = {{0.f,0.f,0.f,0.f},{0.f,0.f,0.f,0.f}};
    const int kko = (w >= 8) ? 4 : 0;
    const int n0v = (w & 7) * 8;
    stage_v(0, 0);
    cp_commit();
    for (int c = 0; c < 8; c++) {
        const int buf = c & 1;
        __syncthreads();
        if (c + 1 < 8) { stage_v(c + 1, buf ^ 1); cp_commit(); }
        {
            const int idx = t * 8;
            const int row = idx >> 7, col0 = idx & 127;
            const float* s4 = &sc[row * SCST + c * 128 + col0];
            const float4 f0 = *(const float4*)s4;
            const float4 f1 = *(const float4*)(s4 + 4);
            __half2 ph[4];
            ph[0] = __floats2half2_rn(f0.x, f0.y);
            ph[1] = __floats2half2_rn(f0.z, f0.w);
            ph[2] = __floats2half2_rn(f1.x, f1.y);
            ph[3] = __floats2half2_rn(f1.z, f1.w);
            *(uint4*)(smem + O_ATH + (row * ATST + col0) * 2) = *(uint4*)ph;
        }
        if (c + 1 < 8) cp_wait<1>(); else cp_wait<0>();
        __syncthreads();
#pragma unroll
        for (int kk = 0; kk < 4; kk++) {
            const int kkk = kko + kk;
            uint32_t ah[2][4];
#pragma unroll
            for (int mi = 0; mi < 2; mi++) {
                const uint32_t ao = (uint32_t)((mi * 16 + (lane & 15)) * ATST
                                    + kkk * 16 + ((lane >> 4) << 3)) * 2;
                ldsm4(ah[mi][0], ah[mi][1], ah[mi][2], ah[mi][3], sb + O_ATH + ao);
            }
            const uint32_t vo = (uint32_t)((n0v + (lane & 7)) * VST
                                + kkk * 16 + (((lane >> 3) & 1) << 3)) * 2;
            uint32_t vh0, vh1;
            ldsm2(vh0, vh1, sb + O_KVH + buf * KVBUF + vo);
#pragma unroll
            for (int mi = 0; mi < 2; mi++)
                mma_f16(Om[mi], ah[mi], vh0, vh1);
        }
    }
    __syncthreads();
    float* red = (float*)(smem + O_ATH);
    if (w >= 8) {
        float* dst = red + ((w - 8) * 32 + lane) * 8;
#pragma unroll
        for (int mi = 0; mi < 2; mi++)
#pragma unroll
            for (int i = 0; i < 4; i++) dst[mi * 4 + i] = Om[mi][i];
    }
    __syncthreads();
    if (w < 8) {
        const float* srcp = red + (w * 32 + lane) * 8;
#pragma unroll
        for (int mi = 0; mi < 2; mi++)
#pragma unroll
            for (int half = 0; half < 2; half++) {
                const int r = qt * QR + mi * 16 + (lane >> 2) + half * 8;
                const size_t go = ((size_t)b * 1024 + r) * DM + h * 64 + n0v + (lane & 3) * 2;
                const float v0 = Om[mi][half * 2 + 0] + srcp[mi * 4 + half * 2 + 0];
                const float v1 = Om[mi][half * 2 + 1] + srcp[mi * 4 + half * 2 + 1];
                *(__half2*)(ohh + go) = __floats2half2_rn(v0, v1);
            }
    }
}

// ---------------- launch -------------------------------------------------------
extern "C" void kernel_launch(void* const* d_in, const int* in_sizes, int n_in,
                              void* d_out, int out_size)
{
    const float* q    = (const float*)d_in[0];
    const float* k    = (const float*)d_in[1];
    const float* v    = (const float*)d_in[2];
    const float* e    = (const float*)d_in[3];
    const float* mask = (const float*)d_in[4];
    const float* W[8] = { (const float*)d_in[5],  (const float*)d_in[7],
                          (const float*)d_in[9],  (const float*)d_in[11],
                          (const float*)d_in[13], (const float*)d_in[15],
                          (const float*)d_in[17], (const float*)d_in[19] };
    const float* bq  = (const float*)d_in[6];
    const float* bq2 = (const float*)d_in[8];
    const float* bq3 = (const float*)d_in[10];
    const float* bk  = (const float*)d_in[12];
    const float* bk2 = (const float*)d_in[14];
    const float* bk3 = (const float*)d_in[16];
    const float* bv  = (const float*)d_in[18];
    const float* bo  = (const float*)d_in[20];

    float* out  = (float*)d_out;
    float* attw = out + (size_t)BB * 1024 * DM;

    h16 *Wh, *qh, *kh, *eh, *vh, *tqh, *tkh;
    h16 *qph, *kph, *kpl, *vth, *ohh;
    cudaGetSymbolAddress((void**)&Wh,  g_Wh);
    cudaGetSymbolAddress((void**)&qh,  g_qh);
    cudaGetSymbolAddress((void**)&kh,  g_kh);
    cudaGetSymbolAddress((void**)&eh,  g_eh);
    cudaGetSymbolAddress((void**)&vh,  g_vh);
    cudaGetSymbolAddress((void**)&tqh, g_tqh);
    cudaGetSymbolAddress((void**)&tkh, g_tkh);
    cudaGetSymbolAddress((void**)&qph, g_qph);
    cudaGetSymbolAddress((void**)&kph, g_kph); cudaGetSymbolAddress((void**)&kpl, g_kpl);
    cudaGetSymbolAddress((void**)&vth, g_vth);
    cudaGetSymbolAddress((void**)&ohh, g_ohh);

    cudaFuncSetAttribute(gemm_mma, cudaFuncAttributeMaxDynamicSharedMemorySize, GEMM_SMEM);
    cudaFuncSetAttribute(attn_tc,  cudaFuncAttributeMaxDynamicSharedMemorySize, ATT_SMEM);

    {
        CJobs cj;
        cj.j[0] = { q, qh, MQ * DM / 4 };
        cj.j[1] = { k, kh, MQ * DM / 4 };
        cj.j[2] = { e, eh, MQ * DM / 4 };
        cj.j[3] = { v, vh, MV * DM / 4 };
        conv_h_all<<<dim3(256, 1, 4), 256>>>(cj);
    }
    {
        WTJobs wj;
        for (int i = 0; i < 8; i++) wj.W[i] = W[i];
        wj.Th = Wh;
        conv_wT_all<<<dim3(32, 32, 8), dim3(32, 8)>>>(wj);
    }

    const size_t WS = (size_t)DM * DM;
    GemmJob jz = {};

    // launch A: t_q, t_k (dual) + vp — all hi-only weights
    {
        GemmJobs3 g = { { jz, jz, jz } };
        g.j[0] = { qh, Wh + 0 * WS, eh, Wh + 1 * WS,
                   bq, bq2, nullptr, tqh, nullptr, nullptr, MQ, 1 };
        g.j[1] = { kh, Wh + 3 * WS, eh, Wh + 4 * WS,
                   bk, bk2, nullptr, tkh, nullptr, nullptr, MQ, 1 };
        g.j[2] = { vh, Wh + 6 * WS, nullptr, nullptr,
                   bv, nullptr, nullptr, nullptr, nullptr, vth, MV, 0 };
        gemm_mma<<<dim3(8, 33, 3), 512, GEMM_SMEM>>>(g);
    }
    // launch B: qp (hi out), kp (hi+lo out)
    {
        GemmJobs3 g = { { jz, jz, jz } };
        g.j[0] = { tqh, Wh + 2 * WS, nullptr, nullptr,
                   bq3, nullptr, nullptr, qph, nullptr, nullptr, MQ, 0 };
        g.j[1] = { tkh, Wh + 5 * WS, nullptr, nullptr,
                   bk3, nullptr, nullptr, kph, kpl, nullptr, MQ, 0 };
        gemm_mma<<<dim3(8, 33, 2), 512, GEMM_SMEM>>>(g);
    }

    attn_tc<<<dim3(1024 / QR, HH, BB), 512, ATT_SMEM>>>(
        qph, kph, kpl, vth, mask, attw, ohh);

    // launch C: out = oh @ Wo + bo -> fp32
    {
        GemmJobs3 g = { { jz, jz, jz } };
        g.j[0] = { ohh, Wh + 7 * WS, nullptr, nullptr,
                   bo, nullptr, out, nullptr, nullptr, nullptr, MV, 0 };
        gemm_mma<<<dim3(8, 32, 1), 512, GEMM_SMEM>>>(g);
    }
}